// round 2
// baseline (speedup 1.0000x reference)
#include <cuda_runtime.h>
#include <cuda_bf16.h>

#define N_NODES 10000
#define N_EDGES 640000
#define E_TOT   (N_EDGES + N_NODES)   // with self loops = 650000
#define NODE_DIM 64
#define H 128
#define NUM_LAYERS 4

#define TE 128          // edges per block in edge_gemm
#define ZSTRIDE 132     // padded row stride (floats) for shared tiles

// -------- persistent scratch (no allocations allowed) --------
__device__ float g_buf0[N_NODES * H];
__device__ float g_buf1[N_NODES * H];
__device__ float g_A[N_NODES * H];
__device__ float g_B[N_NODES * H];
__device__ int   g_es[E_TOT];
__device__ int   g_ed[E_TOT];
__device__ int   g_is64;

// -------- dtype detection: int64 edge_index has zero high words --------
__global__ void detect_dtype(const int* __restrict__ ei32) {
    __shared__ int sbad;
    if (threadIdx.x == 0) sbad = 0;
    __syncthreads();
    int bad = 0;
    for (int i = threadIdx.x; i < 1024; i += 256) {
        if (ei32[2 * i + 1] != 0) bad = 1;
    }
    if (bad) atomicOr(&sbad, 1);
    __syncthreads();
    if (threadIdx.x == 0) g_is64 = sbad ? 0 : 1;
}

// -------- edge index prep (handles int32 or int64 layout) + self loops --------
__global__ void prep_edges(const void* __restrict__ ei, int* __restrict__ es,
                           int* __restrict__ ed) {
    int i = blockIdx.x * blockDim.x + threadIdx.x;
    if (i < N_EDGES) {
        if (g_is64) {
            const long long* p = (const long long*)ei;
            es[i] = (int)p[i];
            ed[i] = (int)p[N_EDGES + i];
        } else {
            const int* p = (const int*)ei;
            es[i] = p[i];
            ed[i] = p[N_EDGES + i];
        }
    } else if (i < E_TOT) {
        int n = i - N_EDGES;
        es[i] = n;
        ed[i] = n;
    }
}

// -------- h0 = x @ W_emb + b_emb   [10000,64]@[64,128] --------
__global__ void embed_kernel(const float* __restrict__ x, const float* __restrict__ W,
                             const float* __restrict__ b, float* __restrict__ h) {
    __shared__ float sx[16][64];
    int n0 = blockIdx.x * 16;
    for (int i = threadIdx.x; i < 16 * 64; i += 128) {
        sx[i >> 6][i & 63] = x[n0 * 64 + i];
    }
    __syncthreads();
    int c = threadIdx.x;
    float bc = b[c];
    for (int n = 0; n < 16; n++) {
        float acc = bc;
#pragma unroll 16
        for (int k = 0; k < 64; k++) acc = fmaf(sx[n][k], W[k * 128 + c], acc);
        h[(n0 + n) * 128 + c] = acc;
    }
}

// -------- per-layer node transform:
//   A = h @ (W1a - W1b) + b1 ;  B = h @ W1b ;  out_init = -FLT_MAX
__global__ void node_transform(const float* __restrict__ h, const float* __restrict__ W1l,
                               const float* __restrict__ b1l, float* __restrict__ A,
                               float* __restrict__ B, float* __restrict__ out_init) {
    __shared__ float sh[32][128];
    int n0 = blockIdx.x * 32;
    int nmax = N_NODES - n0;
    if (nmax > 32) nmax = 32;
    for (int i = threadIdx.x; i < nmax * 128; i += 128) {
        sh[i >> 7][i & 127] = h[n0 * 128 + i];
    }
    __syncthreads();
    int c = threadIdx.x;
    float a[32], bb[32];
    float bc = b1l[c];
#pragma unroll
    for (int n = 0; n < 32; n++) { a[n] = bc; bb[n] = 0.f; }
    for (int k = 0; k < 128; k++) {
        float wa = W1l[k * 128 + c];
        float wb = W1l[(k + 128) * 128 + c];
        float wd = wa - wb;
#pragma unroll
        for (int n = 0; n < 32; n++) {
            float hv = sh[n][k];
            a[n]  = fmaf(hv, wd, a[n]);
            bb[n] = fmaf(hv, wb, bb[n]);
        }
    }
    for (int n = 0; n < nmax; n++) {
        int r = (n0 + n) * 128 + c;
        A[r] = a[n];
        B[r] = bb[n];
        out_init[r] = -3.4028234663852886e38f;
    }
}

// -------- edge phase: z = relu(A[dst]+B[src]); m = z@W2 + b2; atomic-max into hout[dst]
__global__ __launch_bounds__(512, 1)
void edge_gemm(const float* __restrict__ A, const float* __restrict__ B,
               const float* __restrict__ W2l, const float* __restrict__ b2l,
               const int* __restrict__ esrc, const int* __restrict__ edst,
               float* __restrict__ hout, int etot) {
    extern __shared__ float smem[];
    float* sW = smem;                       // [128][ZSTRIDE] transposed: sW[c][k]
    float* sZ = smem + 128 * ZSTRIDE;       // [TE][ZSTRIDE]
    int*   sE = (int*)(smem + 2 * 128 * ZSTRIDE);  // [0..TE): dst, [TE..2TE): src

    int tid = threadIdx.x;
    int e0 = blockIdx.x * TE;

    if (tid < TE) {
        int e = e0 + tid;
        int s = -1, d = -1;
        if (e < etot) { s = esrc[e]; d = edst[e]; }
        sE[tid] = d;
        sE[TE + tid] = s;
    }
    // load W2 transposed into shared
    for (int i = tid; i < 128 * 128; i += 512) {
        int k = i >> 7, c = i & 127;
        sW[c * ZSTRIDE + k] = W2l[i];
    }
    __syncthreads();
    // build Z
    for (int i = tid; i < TE * 128; i += 512) {
        int e = i >> 7, k = i & 127;
        int d = sE[e];
        float v = 0.f;
        if (d >= 0) {
            int s = sE[TE + e];
            v = fmaxf(A[d * 128 + k] + B[s * 128 + k], 0.f);
        }
        sZ[e * ZSTRIDE + k] = v;
    }
    __syncthreads();

    // GEMM: 128 edges x 128 channels, per-thread tile 4 edges x 8 channels
    int tx = tid & 15;   // channel group: channels tx + 16*j
    int ty = tid >> 4;   // edge group:   edges   ty + 32*i
    float acc[4][8];
#pragma unroll
    for (int j = 0; j < 8; j++) {
        float bv = b2l[tx + 16 * j];
#pragma unroll
        for (int i = 0; i < 4; i++) acc[i][j] = bv;
    }

#pragma unroll 1
    for (int k0 = 0; k0 < 128; k0 += 4) {
        float4 za[4], wa[8];
#pragma unroll
        for (int i = 0; i < 4; i++)
            za[i] = *(const float4*)(sZ + (ty + 32 * i) * ZSTRIDE + k0);
#pragma unroll
        for (int j = 0; j < 8; j++)
            wa[j] = *(const float4*)(sW + (tx + 16 * j) * ZSTRIDE + k0);
#pragma unroll
        for (int i = 0; i < 4; i++) {
#pragma unroll
            for (int j = 0; j < 8; j++) {
                acc[i][j] = fmaf(za[i].x, wa[j].x, acc[i][j]);
                acc[i][j] = fmaf(za[i].y, wa[j].y, acc[i][j]);
                acc[i][j] = fmaf(za[i].z, wa[j].z, acc[i][j]);
                acc[i][j] = fmaf(za[i].w, wa[j].w, acc[i][j]);
            }
        }
    }

    // scatter-max (RED atomics, monotone int encoding for float max)
#pragma unroll
    for (int i = 0; i < 4; i++) {
        int d = sE[ty + 32 * i];
        if (d < 0) continue;
        float* orow = hout + d * 128;
#pragma unroll
        for (int j = 0; j < 8; j++) {
            float v = acc[i][j];
            int c = tx + 16 * j;
            if (v >= 0.f) atomicMax((int*)(orow + c), __float_as_int(v));
            else          atomicMin((unsigned int*)(orow + c), __float_as_uint(v));
        }
    }
}

// -------- final: out = h @ W_fc + b_fc --------
__global__ void final_kernel(const float* __restrict__ h, const float* __restrict__ W,
                             const float* __restrict__ b, float* __restrict__ out) {
    __shared__ float sh[16][128];
    int n0 = blockIdx.x * 16;
    for (int i = threadIdx.x; i < 16 * 128; i += 128) {
        sh[i >> 7][i & 127] = h[n0 * 128 + i];
    }
    __syncthreads();
    int c = threadIdx.x;
    float bc = b[c];
    for (int n = 0; n < 16; n++) {
        float acc = bc;
#pragma unroll 8
        for (int k = 0; k < 128; k++) acc = fmaf(sh[n][k], W[k * 128 + c], acc);
        out[(n0 + n) * 128 + c] = acc;
    }
}

extern "C" void kernel_launch(void* const* d_in, const int* in_sizes, int n_in,
                              void* d_out, int out_size) {
    const float* x    = (const float*)d_in[0];
    const void*  ei   = d_in[1];
    const float* Wemb = (const float*)d_in[2];
    const float* bemb = (const float*)d_in[3];
    const float* W1   = (const float*)d_in[4];
    const float* b1   = (const float*)d_in[5];
    const float* W2   = (const float*)d_in[6];
    const float* b2   = (const float*)d_in[7];
    const float* Wfc  = (const float*)d_in[8];
    const float* bfc  = (const float*)d_in[9];
    float* out = (float*)d_out;

    float *buf0, *buf1, *Ap, *Bp;
    int *es, *ed;
    cudaGetSymbolAddress((void**)&buf0, g_buf0);
    cudaGetSymbolAddress((void**)&buf1, g_buf1);
    cudaGetSymbolAddress((void**)&Ap,   g_A);
    cudaGetSymbolAddress((void**)&Bp,   g_B);
    cudaGetSymbolAddress((void**)&es,   g_es);
    cudaGetSymbolAddress((void**)&ed,   g_ed);

    const int smem_edge = (2 * 128 * ZSTRIDE + 2 * TE) * (int)sizeof(float);
    cudaFuncSetAttribute(edge_gemm, cudaFuncAttributeMaxDynamicSharedMemorySize, smem_edge);

    detect_dtype<<<1, 256>>>((const int*)ei);
    prep_edges<<<(E_TOT + 255) / 256, 256>>>(ei, es, ed);
    embed_kernel<<<N_NODES / 16, 128>>>(x, Wemb, bemb, buf0);

    float* hin = buf0;
    float* hout = buf1;
    for (int l = 0; l < NUM_LAYERS; l++) {
        node_transform<<<(N_NODES + 31) / 32, 128>>>(hin, W1 + l * 2 * H * H, b1 + l * H,
                                                     Ap, Bp, hout);
        edge_gemm<<<(E_TOT + TE - 1) / TE, 512, smem_edge>>>(Ap, Bp, W2 + l * H * H,
                                                             b2 + l * H, es, ed, hout, E_TOT);
        float* t = hin; hin = hout; hout = t;
    }
    final_kernel<<<N_NODES / 16, 128>>>(hin, Wfc, bfc, out);
}

// round 4
// speedup vs baseline: 1.6310x; 1.6310x over previous
#include <cuda_runtime.h>
#include <cuda_bf16.h>
#include <mma.h>
#include <cstdint>

using namespace nvcuda;

#define N_NODES 10000
#define N_EDGES 640000
#define E_TOT   (N_EDGES + N_NODES)   // 650000
#define H 128
#define NUM_LAYERS 4

#define TE 128
#define NT_TILES ((E_TOT + TE - 1) / TE)   // 5079

#define LDW 136   // bf16 elems, W tiles [n][k]
#define LDZ 136   // bf16 elems, Z tiles [e][k]
#define LDD 132   // f32 elems,  D tile  [e][n]

// SMEM byte offsets
#define O_WHI 0u
#define O_WLO (O_WHI + 128u * LDW * 2u)       // 34816
#define O_ZHI (O_WLO + 128u * LDW * 2u)       // 69632
#define O_ZLO (O_ZHI + 128u * LDZ * 2u)       // 104448
#define O_D   (O_ZLO + 128u * LDZ * 2u)       // 139264
#define O_DST (O_D + 128u * LDD * 4u)         // 206848
#define O_BIAS (O_DST + 512u)                 // 207360
#define SMEM_EDGE_BYTES (O_BIAS + 512u)       // 207872

// ---------------- persistent scratch ----------------
__device__ float g_buf0[N_NODES * H];
__device__ float g_buf1[N_NODES * H];
__device__ float g_A[N_NODES * H];
__device__ float g_B[N_NODES * H];
__device__ int   g_es0[E_TOT];
__device__ int   g_ed0[E_TOT];
__device__ int   g_es[E_TOT];   // sorted by dst
__device__ int   g_ed[E_TOT];   // sorted by dst
__device__ int   g_cnt[N_NODES];
__device__ int   g_pos[N_NODES];
__device__ int   g_is64;

// ---------------- edge dtype detect ----------------
__global__ void detect_dtype(const int* __restrict__ ei32) {
    __shared__ int sbad;
    if (threadIdx.x == 0) sbad = 0;
    __syncthreads();
    int bad = 0;
    for (int i = threadIdx.x; i < 1024; i += 256)
        if (ei32[2 * i + 1] != 0) bad = 1;
    if (bad) atomicOr(&sbad, 1);
    __syncthreads();
    if (threadIdx.x == 0) g_is64 = sbad ? 0 : 1;
}

__global__ void zero_cnt() {
    int i = blockIdx.x * blockDim.x + threadIdx.x;
    if (i < N_NODES) g_cnt[i] = 0;
}

// edge prep + histogram of dst
__global__ void prep_edges(const void* __restrict__ ei) {
    int i = blockIdx.x * blockDim.x + threadIdx.x;
    if (i < N_EDGES) {
        int s, d;
        if (g_is64) {
            const long long* p = (const long long*)ei;
            s = (int)p[i];
            d = (int)p[N_EDGES + i];
        } else {
            const int* p = (const int*)ei;
            s = p[i];
            d = p[N_EDGES + i];
        }
        g_es0[i] = s;
        g_ed0[i] = d;
        atomicAdd(&g_cnt[d], 1);
    } else if (i < E_TOT) {
        int n = i - N_EDGES;
        g_es0[i] = n;
        g_ed0[i] = n;
        atomicAdd(&g_cnt[n], 1);
    }
}

// single-block exclusive scan of g_cnt -> g_pos (10 counts per thread)
__global__ void scan_kernel() {
    __shared__ int part[1024];
    int t = threadIdx.x;
    int s = 0;
    int base = t * 10;
    if (t < 1000) {
#pragma unroll
        for (int i = 0; i < 10; i++) s += g_cnt[base + i];
    }
    part[t] = s;
    __syncthreads();
    for (int off = 1; off < 1024; off <<= 1) {
        int v = part[t];
        if (t >= off) v += part[t - off];
        __syncthreads();
        part[t] = v;
        __syncthreads();
    }
    int excl = (t == 0) ? 0 : part[t - 1];
    if (t < 1000) {
        int run = excl;
#pragma unroll
        for (int i = 0; i < 10; i++) {
            int c = g_cnt[base + i];
            g_pos[base + i] = run;
            run += c;
        }
    }
}

__global__ void scatter_kernel() {
    int i = blockIdx.x * blockDim.x + threadIdx.x;
    if (i < E_TOT) {
        int d = g_ed0[i];
        int p = atomicAdd(&g_pos[d], 1);
        g_es[p] = g_es0[i];
        g_ed[p] = d;
    }
}

// ---------------- embed: h0 = x@W_emb + b ----------------
__global__ void embed_kernel(const float* __restrict__ x, const float* __restrict__ W,
                             const float* __restrict__ b, float* __restrict__ h) {
    __shared__ float sx[16][64];
    int n0 = blockIdx.x * 16;
    for (int i = threadIdx.x; i < 16 * 64; i += 128)
        sx[i >> 6][i & 63] = x[n0 * 64 + i];
    __syncthreads();
    int c = threadIdx.x;
    float bc = b[c];
    for (int n = 0; n < 16; n++) {
        float acc = bc;
#pragma unroll 16
        for (int k = 0; k < 64; k++) acc = fmaf(sx[n][k], W[k * 128 + c], acc);
        h[(n0 + n) * 128 + c] = acc;
    }
}

// ---------------- node transform: A = h(W1a-W1b)+b1, B = h W1b, init hout ----------------
__global__ void node_transform(const float* __restrict__ h, const float* __restrict__ W1l,
                               const float* __restrict__ b1l, float* __restrict__ A,
                               float* __restrict__ B, float* __restrict__ out_init) {
    __shared__ float sh[16][128];
    int n0 = blockIdx.x * 16;
    for (int i = threadIdx.x; i < 16 * 128; i += 128)
        sh[i >> 7][i & 127] = h[n0 * 128 + i];
    __syncthreads();
    int c = threadIdx.x;
    float a[16], bb[16];
    float bc = b1l[c];
#pragma unroll
    for (int n = 0; n < 16; n++) { a[n] = bc; bb[n] = 0.f; }
    for (int k = 0; k < 128; k++) {
        float wa = W1l[k * 128 + c];
        float wb = W1l[(k + 128) * 128 + c];
        float wd = wa - wb;
#pragma unroll
        for (int n = 0; n < 16; n++) {
            float hv = sh[n][k];
            a[n]  = fmaf(hv, wd, a[n]);
            bb[n] = fmaf(hv, wb, bb[n]);
        }
    }
#pragma unroll
    for (int n = 0; n < 16; n++) {
        int r = (n0 + n) * 128 + c;
        A[r] = a[n];
        B[r] = bb[n];
        out_init[r] = -3.4028234663852886e38f;
    }
}

// ---------------- edge phase: wmma bf16 3-split + segmented-max epilogue ----------------
__global__ __launch_bounds__(512, 1)
void edge_wmma(const float* __restrict__ A, const float* __restrict__ B,
               const float* __restrict__ W2l, const float* __restrict__ b2l,
               const int* __restrict__ es, const int* __restrict__ ed,
               float* __restrict__ hout) {
    extern __shared__ __align__(16) char sm[];
    __nv_bfloat16* sWhi = (__nv_bfloat16*)(sm + O_WHI);
    __nv_bfloat16* sWlo = (__nv_bfloat16*)(sm + O_WLO);
    __nv_bfloat16* sZhi = (__nv_bfloat16*)(sm + O_ZHI);
    __nv_bfloat16* sZlo = (__nv_bfloat16*)(sm + O_ZLO);
    float* sD    = (float*)(sm + O_D);
    int*   sDst  = (int*)(sm + O_DST);
    float* sBias = (float*)(sm + O_BIAS);

    int tid = threadIdx.x;
    int e0 = blockIdx.x * TE;

    // W2^T split into smem: sW[n][k]
    for (int i = tid; i < H * H; i += 512) {
        int k = i >> 7, n = i & 127;
        float w = W2l[i];
        __nv_bfloat16 hi = __float2bfloat16(w);
        __nv_bfloat16 lo = __float2bfloat16(w - __bfloat162float(hi));
        sWhi[n * LDW + k] = hi;
        sWlo[n * LDW + k] = lo;
    }
    if (tid < 128) {
        int ee = e0 + tid;
        sDst[tid] = (ee < E_TOT) ? ed[ee] : -1;
    } else if (tid < 256) {
        sBias[tid - 128] = b2l[tid - 128];
    }

    // Build Z: 4 threads per edge, each 32 k-channels
    {
        int e = tid >> 2, q = tid & 3;
        int ee = e0 + e;
        bool valid = (ee < E_TOT);
        const float* rowA = valid ? (A + (size_t)__ldg(&ed[ee]) * 128) : A;
        const float* rowB = valid ? (B + (size_t)__ldg(&es[ee]) * 128) : B;
#pragma unroll
        for (int i = 0; i < 8; i++) {
            int k0 = q * 32 + i * 4;
            float4 va = __ldg((const float4*)(rowA + k0));
            float4 vb = __ldg((const float4*)(rowB + k0));
            float v0 = 0.f, v1 = 0.f, v2 = 0.f, v3 = 0.f;
            if (valid) {
                v0 = fmaxf(va.x + vb.x, 0.f);
                v1 = fmaxf(va.y + vb.y, 0.f);
                v2 = fmaxf(va.z + vb.z, 0.f);
                v3 = fmaxf(va.w + vb.w, 0.f);
            }
            __nv_bfloat16 h0 = __float2bfloat16(v0), h1 = __float2bfloat16(v1);
            __nv_bfloat16 h2 = __float2bfloat16(v2), h3 = __float2bfloat16(v3);
            __nv_bfloat16 l0 = __float2bfloat16(v0 - __bfloat162float(h0));
            __nv_bfloat16 l1 = __float2bfloat16(v1 - __bfloat162float(h1));
            __nv_bfloat16 l2 = __float2bfloat16(v2 - __bfloat162float(h2));
            __nv_bfloat16 l3 = __float2bfloat16(v3 - __bfloat162float(h3));
            __nv_bfloat162* ph = (__nv_bfloat162*)(sZhi + e * LDZ + k0);
            __nv_bfloat162* pl = (__nv_bfloat162*)(sZlo + e * LDZ + k0);
            ph[0] = __nv_bfloat162{h0, h1};
            ph[1] = __nv_bfloat162{h2, h3};
            pl[0] = __nv_bfloat162{l0, l1};
            pl[1] = __nv_bfloat162{l2, l3};
        }
    }
    __syncthreads();

    // GEMM: warp w -> edge-row er = w>>1 (16 edges), 4 n-frags at nb
    {
        int w = tid >> 5;
        int er = w >> 1;
        int nb = (w & 1) * 4;
        wmma::fragment<wmma::accumulator, 16, 16, 16, float> acc[4];
#pragma unroll
        for (int j = 0; j < 4; j++) wmma::fill_fragment(acc[j], 0.f);
#pragma unroll
        for (int k0 = 0; k0 < 8; k0++) {
            wmma::fragment<wmma::matrix_a, 16, 16, 16, __nv_bfloat16, wmma::row_major> ah, al;
            wmma::load_matrix_sync(ah, sZhi + er * 16 * LDZ + k0 * 16, LDZ);
            wmma::load_matrix_sync(al, sZlo + er * 16 * LDZ + k0 * 16, LDZ);
#pragma unroll
            for (int j = 0; j < 4; j++) {
                wmma::fragment<wmma::matrix_b, 16, 16, 16, __nv_bfloat16, wmma::col_major> bh, bl;
                wmma::load_matrix_sync(bh, sWhi + (nb + j) * 16 * LDW + k0 * 16, LDW);
                wmma::load_matrix_sync(bl, sWlo + (nb + j) * 16 * LDW + k0 * 16, LDW);
                wmma::mma_sync(acc[j], ah, bh, acc[j]);
                wmma::mma_sync(acc[j], ah, bl, acc[j]);
                wmma::mma_sync(acc[j], al, bh, acc[j]);
            }
        }
#pragma unroll
        for (int j = 0; j < 4; j++)
            wmma::store_matrix_sync(sD + er * 16 * LDD + (nb + j) * 16, acc[j], LDD,
                                    wmma::mem_row_major);
    }
    __syncthreads();

    // Epilogue: segmented max over sorted dst, flush with atomics on boundaries
    {
        int c = tid & 127;
        int q = tid >> 7;        // 0..3, edges [32q, 32q+32)
        float bias = sBias[c];
        int cur = sDst[32 * q];
        float run = -3.4028234663852886e38f;
#pragma unroll 4
        for (int e = 32 * q; e < 32 * q + 32; e++) {
            int d = sDst[e];
            float v = sD[e * LDD + c] + bias;
            if (d != cur) {
                if (cur >= 0) {
                    float* p = hout + (size_t)cur * 128 + c;
                    if (run >= 0.f) atomicMax((int*)p, __float_as_int(run));
                    else            atomicMin((unsigned int*)p, __float_as_uint(run));
                }
                cur = d;
                run = v;
            } else {
                run = fmaxf(run, v);
            }
        }
        if (cur >= 0) {
            float* p = hout + (size_t)cur * 128 + c;
            if (run >= 0.f) atomicMax((int*)p, __float_as_int(run));
            else            atomicMin((unsigned int*)p, __float_as_uint(run));
        }
    }
}

// ---------------- final: out = h@W_fc + b ----------------
__global__ void final_kernel(const float* __restrict__ h, const float* __restrict__ W,
                             const float* __restrict__ b, float* __restrict__ out) {
    __shared__ float sh[16][128];
    int n0 = blockIdx.x * 16;
    for (int i = threadIdx.x; i < 16 * 128; i += 128)
        sh[i >> 7][i & 127] = h[n0 * 128 + i];
    __syncthreads();
    int c = threadIdx.x;
    float bc = b[c];
    for (int n = 0; n < 16; n++) {
        float acc = bc;
#pragma unroll 8
        for (int k = 0; k < 128; k++) acc = fmaf(sh[n][k], W[k * 128 + c], acc);
        out[(n0 + n) * 128 + c] = acc;
    }
}

extern "C" void kernel_launch(void* const* d_in, const int* in_sizes, int n_in,
                              void* d_out, int out_size) {
    const float* x    = (const float*)d_in[0];
    const void*  ei   = d_in[1];
    const float* Wemb = (const float*)d_in[2];
    const float* bemb = (const float*)d_in[3];
    const float* W1   = (const float*)d_in[4];
    const float* b1   = (const float*)d_in[5];
    const float* W2   = (const float*)d_in[6];
    const float* b2   = (const float*)d_in[7];
    const float* Wfc  = (const float*)d_in[8];
    const float* bfc  = (const float*)d_in[9];
    float* out = (float*)d_out;

    float *buf0, *buf1, *Ap, *Bp;
    int *es, *ed;
    cudaGetSymbolAddress((void**)&buf0, g_buf0);
    cudaGetSymbolAddress((void**)&buf1, g_buf1);
    cudaGetSymbolAddress((void**)&Ap,   g_A);
    cudaGetSymbolAddress((void**)&Bp,   g_B);
    cudaGetSymbolAddress((void**)&es,   g_es);
    cudaGetSymbolAddress((void**)&ed,   g_ed);

    cudaFuncSetAttribute(edge_wmma, cudaFuncAttributeMaxDynamicSharedMemorySize,
                         SMEM_EDGE_BYTES);

    detect_dtype<<<1, 256>>>((const int*)ei);
    zero_cnt<<<(N_NODES + 255) / 256, 256>>>();
    prep_edges<<<(E_TOT + 255) / 256, 256>>>(ei);
    scan_kernel<<<1, 1024>>>();
    scatter_kernel<<<(E_TOT + 255) / 256, 256>>>();
    embed_kernel<<<N_NODES / 16, 128>>>(x, Wemb, bemb, buf0);

    float* hin = buf0;
    float* hout = buf1;
    for (int l = 0; l < NUM_LAYERS; l++) {
        node_transform<<<N_NODES / 16, 128>>>(hin, W1 + l * 2 * H * H, b1 + l * H,
                                              Ap, Bp, hout);
        edge_wmma<<<NT_TILES, 512, SMEM_EDGE_BYTES>>>(Ap, Bp, W2 + l * H * H,
                                                      b2 + l * H, es, ed, hout);
        float* t = hin; hin = hout; hout = t;
    }
    final_kernel<<<N_NODES / 16, 128>>>(hin, Wfc, bfc, out);
}

// round 6
// speedup vs baseline: 1.8981x; 1.1638x over previous
#include <cuda_runtime.h>
#include <cuda_bf16.h>
#include <mma.h>
#include <cstdint>

using namespace nvcuda;

#define N_NODES 10000
#define N_EDGES 640000
#define E_TOT   (N_EDGES + N_NODES)   // 650000
#define H 128
#define NUM_LAYERS 4

#define TE 128
#define NT_TILES ((E_TOT + TE - 1) / TE)   // 5079
#define GRID_EDGE 148

#define LDW 136   // bf16 elems, W tiles [n][k]
#define LDZ 136   // bf16 elems, Z tiles [e][k]
#define LDD 132   // f32 elems,  D tile  [e][n]

// SMEM byte offsets
#define O_WHI 0u
#define O_WLO (O_WHI + 128u * LDW * 2u)       // 34816
#define O_ZHI (O_WLO + 128u * LDW * 2u)       // 69632
#define O_ZLO (O_ZHI + 128u * LDZ * 2u)       // 104448
#define O_D   (O_ZLO + 128u * LDZ * 2u)       // 139264
#define O_DST (O_D + 128u * LDD * 4u)         // 206848  (2 x 128 ints)
#define O_BIAS (O_DST + 1024u)                // 207872
#define SMEM_EDGE_BYTES (O_BIAS + 512u)       // 208384

// ---------------- persistent scratch ----------------
__device__ float g_buf0[N_NODES * H];
__device__ float g_buf1[N_NODES * H];
__device__ float g_A[N_NODES * H];
__device__ float g_B[N_NODES * H];
__device__ int   g_es0[E_TOT];
__device__ int   g_ed0[E_TOT];
__device__ int   g_es[E_TOT];   // sorted by dst
__device__ int   g_ed[E_TOT];   // sorted by dst
__device__ int   g_cnt[N_NODES];
__device__ int   g_pos[N_NODES];
__device__ int   g_is64;

// ---------------- edge dtype detect ----------------
__global__ void detect_dtype(const int* __restrict__ ei32) {
    __shared__ int sbad;
    if (threadIdx.x == 0) sbad = 0;
    __syncthreads();
    int bad = 0;
    for (int i = threadIdx.x; i < 1024; i += 256)
        if (ei32[2 * i + 1] != 0) bad = 1;
    if (bad) atomicOr(&sbad, 1);
    __syncthreads();
    if (threadIdx.x == 0) g_is64 = sbad ? 0 : 1;
}

__global__ void zero_cnt() {
    int i = blockIdx.x * blockDim.x + threadIdx.x;
    if (i < N_NODES) g_cnt[i] = 0;
}

// edge prep + histogram of dst
__global__ void prep_edges(const void* __restrict__ ei) {
    int i = blockIdx.x * blockDim.x + threadIdx.x;
    if (i < N_EDGES) {
        int s, d;
        if (g_is64) {
            const long long* p = (const long long*)ei;
            s = (int)p[i];
            d = (int)p[N_EDGES + i];
        } else {
            const int* p = (const int*)ei;
            s = p[i];
            d = p[N_EDGES + i];
        }
        g_es0[i] = s;
        g_ed0[i] = d;
        atomicAdd(&g_cnt[d], 1);
    } else if (i < E_TOT) {
        int n = i - N_EDGES;
        g_es0[i] = n;
        g_ed0[i] = n;
        atomicAdd(&g_cnt[n], 1);
    }
}

// single-block exclusive scan of g_cnt -> g_pos
__global__ void scan_kernel() {
    __shared__ int part[1024];
    int t = threadIdx.x;
    int s = 0;
    int base = t * 10;
    if (t < 1000) {
#pragma unroll
        for (int i = 0; i < 10; i++) s += g_cnt[base + i];
    }
    part[t] = s;
    __syncthreads();
    for (int off = 1; off < 1024; off <<= 1) {
        int v = part[t];
        if (t >= off) v += part[t - off];
        __syncthreads();
        part[t] = v;
        __syncthreads();
    }
    int excl = (t == 0) ? 0 : part[t - 1];
    if (t < 1000) {
        int run = excl;
#pragma unroll
        for (int i = 0; i < 10; i++) {
            int c = g_cnt[base + i];
            g_pos[base + i] = run;
            run += c;
        }
    }
}

__global__ void scatter_kernel() {
    int i = blockIdx.x * blockDim.x + threadIdx.x;
    if (i < E_TOT) {
        int d = g_ed0[i];
        int p = atomicAdd(&g_pos[d], 1);
        g_es[p] = g_es0[i];
        g_ed[p] = d;
    }
}

// ---------------- embed: h0 = x@W_emb + b ----------------
__global__ void embed_kernel(const float* __restrict__ x, const float* __restrict__ W,
                             const float* __restrict__ b, float* __restrict__ h) {
    __shared__ float sx[16][64];
    int n0 = blockIdx.x * 16;
    for (int i = threadIdx.x; i < 16 * 64; i += 128)
        sx[i >> 6][i & 63] = x[n0 * 64 + i];
    __syncthreads();
    int c = threadIdx.x;
    float bc = b[c];
    for (int n = 0; n < 16; n++) {
        float acc = bc;
#pragma unroll 16
        for (int k = 0; k < 64; k++) acc = fmaf(sx[n][k], W[k * 128 + c], acc);
        h[(n0 + n) * 128 + c] = acc;
    }
}

// ---------------- node transform (256 thr): A = h(W1a-W1b)+b1, B = h W1b ----------------
__global__ void node_transform(const float* __restrict__ h, const float* __restrict__ W1l,
                               const float* __restrict__ b1l, float* __restrict__ A,
                               float* __restrict__ B, float* __restrict__ out_init) {
    __shared__ float sh[16][128];
    int n0 = blockIdx.x * 16;
    for (int i = threadIdx.x; i < 16 * 128; i += 256)
        sh[i >> 7][i & 127] = h[n0 * 128 + i];
    __syncthreads();
    int c = threadIdx.x & 127;
    int nh = (threadIdx.x >> 7) * 8;   // node half: 0 or 8
    float a[8], bb[8];
    float bc = b1l[c];
#pragma unroll
    for (int n = 0; n < 8; n++) { a[n] = bc; bb[n] = 0.f; }
    for (int k = 0; k < 128; k++) {
        float wa = W1l[k * 128 + c];
        float wb = W1l[(k + 128) * 128 + c];
        float wd = wa - wb;
#pragma unroll
        for (int n = 0; n < 8; n++) {
            float hv = sh[nh + n][k];
            a[n]  = fmaf(hv, wd, a[n]);
            bb[n] = fmaf(hv, wb, bb[n]);
        }
    }
#pragma unroll
    for (int n = 0; n < 8; n++) {
        int r = (n0 + nh + n) * 128 + c;
        A[r] = a[n];
        B[r] = bb[n];
        out_init[r] = -3.4028234663852886e38f;
    }
}

// ---------------- persistent edge phase ----------------
__global__ __launch_bounds__(512, 1)
void edge_persist(const float* __restrict__ A, const float* __restrict__ B,
                  const float* __restrict__ W2l, const float* __restrict__ b2l,
                  const int* __restrict__ es, const int* __restrict__ ed,
                  float* __restrict__ hout) {
    extern __shared__ __align__(16) char sm[];
    __nv_bfloat16* sWhi = (__nv_bfloat16*)(sm + O_WHI);
    __nv_bfloat16* sWlo = (__nv_bfloat16*)(sm + O_WLO);
    __nv_bfloat16* sZhi = (__nv_bfloat16*)(sm + O_ZHI);
    __nv_bfloat16* sZlo = (__nv_bfloat16*)(sm + O_ZLO);
    float* sD    = (float*)(sm + O_D);
    int*   sDst  = (int*)(sm + O_DST);     // [2][128]
    float* sBias = (float*)(sm + O_BIAS);

    int tid = threadIdx.x;

    // one-time setup: W2^T split into smem: sW[n][k]
    for (int i = tid; i < H * H; i += 512) {
        int k = i >> 7, n = i & 127;
        float w = W2l[i];
        __nv_bfloat16 hi = __float2bfloat16(w);
        __nv_bfloat16 lo = __float2bfloat16(w - __bfloat162float(hi));
        sWhi[n * LDW + k] = hi;
        sWlo[n * LDW + k] = lo;
    }
    if (tid < 128) sBias[tid] = b2l[tid];
    __syncthreads();

    // warp GEMM mapping
    int w = tid >> 5;
    int er = w >> 1;
    int nb = (w & 1) * 4;

    // build lambda: gather + split tile t into Z, dst ring buf
    auto build = [&](int t, int buf) {
        int e0 = t * TE;
        if (tid < 128) {
            int ee = e0 + tid;
            sDst[buf * 128 + tid] = (ee < E_TOT) ? __ldg(&ed[ee]) : -1;
        }
        int e = tid >> 2, q = tid & 3;
        int ee = e0 + e;
        bool valid = (ee < E_TOT);
        const float* rowA = valid ? (A + (size_t)__ldg(&ed[ee]) * 128) : A;
        const float* rowB = valid ? (B + (size_t)__ldg(&es[ee]) * 128) : B;
#pragma unroll
        for (int i = 0; i < 8; i++) {
            int k0 = q * 32 + i * 4;
            float4 va = __ldg((const float4*)(rowA + k0));
            float4 vb = __ldg((const float4*)(rowB + k0));
            float v0 = 0.f, v1 = 0.f, v2 = 0.f, v3 = 0.f;
            if (valid) {
                v0 = fmaxf(va.x + vb.x, 0.f);
                v1 = fmaxf(va.y + vb.y, 0.f);
                v2 = fmaxf(va.z + vb.z, 0.f);
                v3 = fmaxf(va.w + vb.w, 0.f);
            }
            __nv_bfloat162 h01 = __floats2bfloat162_rn(v0, v1);
            __nv_bfloat162 h23 = __floats2bfloat162_rn(v2, v3);
            __nv_bfloat162 l01 = __floats2bfloat162_rn(v0 - __bfloat162float(h01.x),
                                                       v1 - __bfloat162float(h01.y));
            __nv_bfloat162 l23 = __floats2bfloat162_rn(v2 - __bfloat162float(h23.x),
                                                       v3 - __bfloat162float(h23.y));
            __nv_bfloat162* ph = (__nv_bfloat162*)(sZhi + e * LDZ + k0);
            __nv_bfloat162* pl = (__nv_bfloat162*)(sZlo + e * LDZ + k0);
            ph[0] = h01; ph[1] = h23;
            pl[0] = l01; pl[1] = l23;
        }
    };

    // epilogue lambda: segmented atomic max from sD using dst ring buf
    auto epilogue = [&](int buf) {
        int c = tid & 127;
        int q = tid >> 7;
        float bias = sBias[c];
        const int* dstb = sDst + buf * 128;
        int cur = dstb[32 * q];
        float run = -3.4028234663852886e38f;
#pragma unroll 4
        for (int e = 32 * q; e < 32 * q + 32; e++) {
            int d = dstb[e];
            float v = sD[e * LDD + c] + bias;
            if (d != cur) {
                if (cur >= 0) {
                    float* p = hout + (size_t)cur * 128 + c;
                    if (run >= 0.f) atomicMax((int*)p, __float_as_int(run));
                    else            atomicMin((unsigned int*)p, __float_as_uint(run));
                }
                cur = d;
                run = v;
            } else {
                run = fmaxf(run, v);
            }
        }
        if (cur >= 0) {
            float* p = hout + (size_t)cur * 128 + c;
            if (run >= 0.f) atomicMax((int*)p, __float_as_int(run));
            else            atomicMin((unsigned int*)p, __float_as_uint(run));
        }
    };

    auto gemm = [&]() {
        wmma::fragment<wmma::accumulator, 16, 16, 16, float> acc[4];
#pragma unroll
        for (int j = 0; j < 4; j++) wmma::fill_fragment(acc[j], 0.f);
#pragma unroll
        for (int k0 = 0; k0 < 8; k0++) {
            wmma::fragment<wmma::matrix_a, 16, 16, 16, __nv_bfloat16, wmma::row_major> ah, al;
            wmma::load_matrix_sync(ah, sZhi + er * 16 * LDZ + k0 * 16, LDZ);
            wmma::load_matrix_sync(al, sZlo + er * 16 * LDZ + k0 * 16, LDZ);
#pragma unroll
            for (int j = 0; j < 4; j++) {
                wmma::fragment<wmma::matrix_b, 16, 16, 16, __nv_bfloat16, wmma::col_major> bh, bl;
                wmma::load_matrix_sync(bh, sWhi + (nb + j) * 16 * LDW + k0 * 16, LDW);
                wmma::load_matrix_sync(bl, sWlo + (nb + j) * 16 * LDW + k0 * 16, LDW);
                wmma::mma_sync(acc[j], ah, bh, acc[j]);
                wmma::mma_sync(acc[j], ah, bl, acc[j]);
                wmma::mma_sync(acc[j], al, bh, acc[j]);
            }
        }
#pragma unroll
        for (int j = 0; j < 4; j++)
            wmma::store_matrix_sync(sD + er * 16 * LDD + (nb + j) * 16, acc[j], LDD,
                                    wmma::mem_row_major);
    };

    int it = 0;
    for (int t = blockIdx.x; t < NT_TILES; t += GRID_EDGE, it++) {
        // phase 1: build current tile; overlap epilogue of previous tile
        build(t, it & 1);
        if (it > 0) epilogue((it - 1) & 1);
        __syncthreads();
        // phase 2: tensor GEMM into sD
        gemm();
        __syncthreads();
    }
    if (it > 0) epilogue((it - 1) & 1);
}

// ---------------- final: out = h@W_fc + b ----------------
__global__ void final_kernel(const float* __restrict__ h, const float* __restrict__ W,
                             const float* __restrict__ b, float* __restrict__ out) {
    __shared__ float sh[16][128];
    int n0 = blockIdx.x * 16;
    for (int i = threadIdx.x; i < 16 * 128; i += 128)
        sh[i >> 7][i & 127] = h[n0 * 128 + i];
    __syncthreads();
    int c = threadIdx.x;
    float bc = b[c];
    for (int n = 0; n < 16; n++) {
        float acc = bc;
#pragma unroll 8
        for (int k = 0; k < 128; k++) acc = fmaf(sh[n][k], W[k * 128 + c], acc);
        out[(n0 + n) * 128 + c] = acc;
    }
}

extern "C" void kernel_launch(void* const* d_in, const int* in_sizes, int n_in,
                              void* d_out, int out_size) {
    const float* x    = (const float*)d_in[0];
    const void*  ei   = d_in[1];
    const float* Wemb = (const float*)d_in[2];
    const float* bemb = (const float*)d_in[3];
    const float* W1   = (const float*)d_in[4];
    const float* b1   = (const float*)d_in[5];
    const float* W2   = (const float*)d_in[6];
    const float* b2   = (const float*)d_in[7];
    const float* Wfc  = (const float*)d_in[8];
    const float* bfc  = (const float*)d_in[9];
    float* out = (float*)d_out;

    float *buf0, *buf1, *Ap, *Bp;
    int *es, *ed;
    cudaGetSymbolAddress((void**)&buf0, g_buf0);
    cudaGetSymbolAddress((void**)&buf1, g_buf1);
    cudaGetSymbolAddress((void**)&Ap,   g_A);
    cudaGetSymbolAddress((void**)&Bp,   g_B);
    cudaGetSymbolAddress((void**)&es,   g_es);
    cudaGetSymbolAddress((void**)&ed,   g_ed);

    cudaFuncSetAttribute(edge_persist, cudaFuncAttributeMaxDynamicSharedMemorySize,
                         SMEM_EDGE_BYTES);

    detect_dtype<<<1, 256>>>((const int*)ei);
    zero_cnt<<<(N_NODES + 255) / 256, 256>>>();
    prep_edges<<<(E_TOT + 255) / 256, 256>>>(ei);
    scan_kernel<<<1, 1024>>>();
    scatter_kernel<<<(E_TOT + 255) / 256, 256>>>();
    embed_kernel<<<N_NODES / 16, 128>>>(x, Wemb, bemb, buf0);

    float* hin = buf0;
    float* hout = buf1;
    for (int l = 0; l < NUM_LAYERS; l++) {
        node_transform<<<N_NODES / 16, 256>>>(hin, W1 + l * 2 * H * H, b1 + l * H,
                                              Ap, Bp, hout);
        edge_persist<<<GRID_EDGE, 512, SMEM_EDGE_BYTES>>>(Ap, Bp, W2 + l * H * H,
                                                          b2 + l * H, es, ed, hout);
        float* t = hin; hin = hout; hout = t;
    }
    final_kernel<<<N_NODES / 16, 128>>>(hin, Wfc, bfc, out);
}

// round 7
// speedup vs baseline: 2.0261x; 1.0674x over previous
#include <cuda_runtime.h>
#include <cuda_bf16.h>
#include <mma.h>
#include <cstdint>

using namespace nvcuda;

#define N_NODES 10000
#define N_EDGES 640000
#define E_TOT   (N_EDGES + N_NODES)   // 650000
#define H 128
#define NUM_LAYERS 4

#define TE 128
#define NT_TILES ((E_TOT + TE - 1) / TE)   // 5079
#define GRID_EDGE 148

#define LDW 136   // bf16 elems, W tiles [n][k]
#define LDZ 136   // bf16 elems, Z tiles [e][k]
#define LDD 132   // f32 elems,  D tile  [e][n]

// SMEM byte offsets
#define O_WHI 0u
#define O_WLO (O_WHI + 128u * LDW * 2u)       // 34816
#define O_ZHI (O_WLO + 128u * LDW * 2u)       // 69632
#define O_ZLO (O_ZHI + 128u * LDZ * 2u)       // 104448
#define O_D   (O_ZLO + 128u * LDZ * 2u)       // 139264
#define O_DST (O_D + 128u * LDD * 4u)         // 206848  (2 x 128 ints)
#define O_BIAS (O_DST + 1024u)                // 207872
#define SMEM_EDGE_BYTES (O_BIAS + 512u)       // 208384

// ---------------- persistent scratch ----------------
__device__ float g_buf0[N_NODES * H];
__device__ float g_buf1[N_NODES * H];
__device__ float g_A[N_NODES * H];
__device__ float g_B[N_NODES * H];
__device__ int   g_es0[E_TOT];
__device__ int   g_ed0[E_TOT];
__device__ int   g_es[E_TOT];   // sorted by dst
__device__ int   g_ed[E_TOT];   // sorted by dst
__device__ int   g_cnt[N_NODES];
__device__ int   g_pos[N_NODES];
__device__ int   g_is64;

// ---------------- edge dtype detect ----------------
__global__ void detect_dtype(const int* __restrict__ ei32) {
    __shared__ int sbad;
    if (threadIdx.x == 0) sbad = 0;
    __syncthreads();
    int bad = 0;
    for (int i = threadIdx.x; i < 1024; i += 256)
        if (ei32[2 * i + 1] != 0) bad = 1;
    if (bad) atomicOr(&sbad, 1);
    __syncthreads();
    if (threadIdx.x == 0) g_is64 = sbad ? 0 : 1;
}

__global__ void zero_cnt() {
    int i = blockIdx.x * blockDim.x + threadIdx.x;
    if (i < N_NODES) g_cnt[i] = 0;
}

// edge prep + histogram of dst
__global__ void prep_edges(const void* __restrict__ ei) {
    int i = blockIdx.x * blockDim.x + threadIdx.x;
    if (i < N_EDGES) {
        int s, d;
        if (g_is64) {
            const long long* p = (const long long*)ei;
            s = (int)p[i];
            d = (int)p[N_EDGES + i];
        } else {
            const int* p = (const int*)ei;
            s = p[i];
            d = p[N_EDGES + i];
        }
        g_es0[i] = s;
        g_ed0[i] = d;
        atomicAdd(&g_cnt[d], 1);
    } else if (i < E_TOT) {
        int n = i - N_EDGES;
        g_es0[i] = n;
        g_ed0[i] = n;
        atomicAdd(&g_cnt[n], 1);
    }
}

// single-block exclusive scan of g_cnt -> g_pos
__global__ void scan_kernel() {
    __shared__ int part[1024];
    int t = threadIdx.x;
    int s = 0;
    int base = t * 10;
    if (t < 1000) {
#pragma unroll
        for (int i = 0; i < 10; i++) s += g_cnt[base + i];
    }
    part[t] = s;
    __syncthreads();
    for (int off = 1; off < 1024; off <<= 1) {
        int v = part[t];
        if (t >= off) v += part[t - off];
        __syncthreads();
        part[t] = v;
        __syncthreads();
    }
    int excl = (t == 0) ? 0 : part[t - 1];
    if (t < 1000) {
        int run = excl;
#pragma unroll
        for (int i = 0; i < 10; i++) {
            int c = g_cnt[base + i];
            g_pos[base + i] = run;
            run += c;
        }
    }
}

__global__ void scatter_kernel() {
    int i = blockIdx.x * blockDim.x + threadIdx.x;
    if (i < E_TOT) {
        int d = g_ed0[i];
        int p = atomicAdd(&g_pos[d], 1);
        g_es[p] = g_es0[i];
        g_ed[p] = d;
    }
}

// ---------------- embed: h0 = x@W_emb + b ----------------
__global__ void embed_kernel(const float* __restrict__ x, const float* __restrict__ W,
                             const float* __restrict__ b, float* __restrict__ h) {
    __shared__ float sx[16][64];
    int n0 = blockIdx.x * 16;
    for (int i = threadIdx.x; i < 16 * 64; i += 128)
        sx[i >> 6][i & 63] = x[n0 * 64 + i];
    __syncthreads();
    int c = threadIdx.x;
    float bc = b[c];
    for (int n = 0; n < 16; n++) {
        float acc = bc;
#pragma unroll 16
        for (int k = 0; k < 64; k++) acc = fmaf(sx[n][k], W[k * 128 + c], acc);
        h[(n0 + n) * 128 + c] = acc;
    }
}

// ---------------- node transform (256 thr): A = h(W1a-W1b)+b1, B = h W1b ----------------
__global__ void node_transform(const float* __restrict__ h, const float* __restrict__ W1l,
                               const float* __restrict__ b1l, float* __restrict__ A,
                               float* __restrict__ B, float* __restrict__ out_init) {
    __shared__ float sh[16][128];
    int n0 = blockIdx.x * 16;
    for (int i = threadIdx.x; i < 16 * 128; i += 256)
        sh[i >> 7][i & 127] = h[n0 * 128 + i];
    __syncthreads();
    int c = threadIdx.x & 127;
    int nh = (threadIdx.x >> 7) * 8;   // node half: 0 or 8
    float a[8], bb[8];
    float bc = b1l[c];
#pragma unroll
    for (int n = 0; n < 8; n++) { a[n] = bc; bb[n] = 0.f; }
    for (int k = 0; k < 128; k++) {
        float wa = W1l[k * 128 + c];
        float wb = W1l[(k + 128) * 128 + c];
        float wd = wa - wb;
#pragma unroll
        for (int n = 0; n < 8; n++) {
            float hv = sh[nh + n][k];
            a[n]  = fmaf(hv, wd, a[n]);
            bb[n] = fmaf(hv, wb, bb[n]);
        }
    }
#pragma unroll
    for (int n = 0; n < 8; n++) {
        int r = (n0 + nh + n) * 128 + c;
        A[r] = a[n];
        B[r] = bb[n];
        out_init[r] = -3.4028234663852886e38f;
    }
}

// ---------------- persistent edge phase (256 thr, W2 frags in registers) ----------------
__global__ __launch_bounds__(256, 1)
void edge_persist(const float* __restrict__ A, const float* __restrict__ B,
                  const float* __restrict__ W2l, const float* __restrict__ b2l,
                  const int* __restrict__ es, const int* __restrict__ ed,
                  float* __restrict__ hout) {
    extern __shared__ __align__(16) char sm[];
    __nv_bfloat16* sWhi = (__nv_bfloat16*)(sm + O_WHI);
    __nv_bfloat16* sWlo = (__nv_bfloat16*)(sm + O_WLO);
    __nv_bfloat16* sZhi = (__nv_bfloat16*)(sm + O_ZHI);
    __nv_bfloat16* sZlo = (__nv_bfloat16*)(sm + O_ZLO);
    float* sD    = (float*)(sm + O_D);
    int*   sDst  = (int*)(sm + O_DST);     // [2][128]
    float* sBias = (float*)(sm + O_BIAS);

    int tid = threadIdx.x;

    // one-time setup: W2^T split into smem: sW[n][k]
    for (int i = tid; i < H * H; i += 256) {
        int k = i >> 7, n = i & 127;
        float w = W2l[i];
        __nv_bfloat16 hi = __float2bfloat16(w);
        __nv_bfloat16 lo = __float2bfloat16(w - __bfloat162float(hi));
        sWhi[n * LDW + k] = hi;
        sWlo[n * LDW + k] = lo;
    }
    if (tid < 128) sBias[tid] = b2l[tid];
    __syncthreads();

    // warp GEMM mapping: 8 warps; jg = w&3 (cols jg*32..+32), eg = w>>2 (edges eg*64..+64)
    int w = tid >> 5;
    int jg = w & 3;
    int eg = w >> 2;

    // register-cache ALL W2 fragments for this warp's 2 j-frags x 8 k-steps (hi+lo)
    wmma::fragment<wmma::matrix_b, 16, 16, 16, __nv_bfloat16, wmma::col_major> Bh[8][2], Bl[8][2];
#pragma unroll
    for (int k0 = 0; k0 < 8; k0++) {
#pragma unroll
        for (int s = 0; s < 2; s++) {
            wmma::load_matrix_sync(Bh[k0][s], sWhi + (jg * 2 + s) * 16 * LDW + k0 * 16, LDW);
            wmma::load_matrix_sync(Bl[k0][s], sWlo + (jg * 2 + s) * 16 * LDW + k0 * 16, LDW);
        }
    }

    // build: 2 threads per edge, 64 channels each
    auto build = [&](int t, int buf) {
        int e0 = t * TE;
        if (tid < 128) {
            int ee = e0 + tid;
            sDst[buf * 128 + tid] = (ee < E_TOT) ? __ldg(&ed[ee]) : -1;
        }
        int e = tid >> 1, q = tid & 1;
        int ee = e0 + e;
        bool valid = (ee < E_TOT);
        const float* rowA = valid ? (A + (size_t)__ldg(&ed[ee]) * 128) : A;
        const float* rowB = valid ? (B + (size_t)__ldg(&es[ee]) * 128) : B;
#pragma unroll
        for (int i = 0; i < 16; i++) {
            int k0 = q * 64 + i * 4;
            float4 va = __ldg((const float4*)(rowA + k0));
            float4 vb = __ldg((const float4*)(rowB + k0));
            float v0 = 0.f, v1 = 0.f, v2 = 0.f, v3 = 0.f;
            if (valid) {
                v0 = fmaxf(va.x + vb.x, 0.f);
                v1 = fmaxf(va.y + vb.y, 0.f);
                v2 = fmaxf(va.z + vb.z, 0.f);
                v3 = fmaxf(va.w + vb.w, 0.f);
            }
            __nv_bfloat162 h01 = __floats2bfloat162_rn(v0, v1);
            __nv_bfloat162 h23 = __floats2bfloat162_rn(v2, v3);
            __nv_bfloat162 l01 = __floats2bfloat162_rn(v0 - __bfloat162float(h01.x),
                                                       v1 - __bfloat162float(h01.y));
            __nv_bfloat162 l23 = __floats2bfloat162_rn(v2 - __bfloat162float(h23.x),
                                                       v3 - __bfloat162float(h23.y));
            __nv_bfloat162* ph = (__nv_bfloat162*)(sZhi + e * LDZ + k0);
            __nv_bfloat162* pl = (__nv_bfloat162*)(sZlo + e * LDZ + k0);
            ph[0] = h01; ph[1] = h23;
            pl[0] = l01; pl[1] = l23;
        }
    };

    // epilogue: 2 q-halves of 64 edges, segmented atomic max
    auto epilogue = [&](int buf) {
        int c = tid & 127;
        int q = tid >> 7;          // 0 or 1
        float bias = sBias[c];
        const int* dstb = sDst + buf * 128;
        int cur = dstb[64 * q];
        float run = -3.4028234663852886e38f;
#pragma unroll 4
        for (int e = 64 * q; e < 64 * q + 64; e++) {
            int d = dstb[e];
            float v = sD[e * LDD + c] + bias;
            if (d != cur) {
                if (cur >= 0) {
                    float* p = hout + (size_t)cur * 128 + c;
                    if (run >= 0.f) atomicMax((int*)p, __float_as_int(run));
                    else            atomicMin((unsigned int*)p, __float_as_uint(run));
                }
                cur = d;
                run = v;
            } else {
                run = fmaxf(run, v);
            }
        }
        if (cur >= 0) {
            float* p = hout + (size_t)cur * 128 + c;
            if (run >= 0.f) atomicMax((int*)p, __float_as_int(run));
            else            atomicMin((unsigned int*)p, __float_as_uint(run));
        }
    };

    auto gemm = [&]() {
        wmma::fragment<wmma::accumulator, 16, 16, 16, float> acc[4][2];
#pragma unroll
        for (int r = 0; r < 4; r++)
#pragma unroll
            for (int s = 0; s < 2; s++) wmma::fill_fragment(acc[r][s], 0.f);
#pragma unroll
        for (int k0 = 0; k0 < 8; k0++) {
            wmma::fragment<wmma::matrix_a, 16, 16, 16, __nv_bfloat16, wmma::row_major> ah[4], al[4];
#pragma unroll
            for (int r = 0; r < 4; r++) {
                wmma::load_matrix_sync(ah[r], sZhi + (eg * 4 + r) * 16 * LDZ + k0 * 16, LDZ);
                wmma::load_matrix_sync(al[r], sZlo + (eg * 4 + r) * 16 * LDZ + k0 * 16, LDZ);
            }
#pragma unroll
            for (int r = 0; r < 4; r++) {
#pragma unroll
                for (int s = 0; s < 2; s++) {
                    wmma::mma_sync(acc[r][s], ah[r], Bh[k0][s], acc[r][s]);
                    wmma::mma_sync(acc[r][s], ah[r], Bl[k0][s], acc[r][s]);
                    wmma::mma_sync(acc[r][s], al[r], Bh[k0][s], acc[r][s]);
                }
            }
        }
#pragma unroll
        for (int r = 0; r < 4; r++)
#pragma unroll
            for (int s = 0; s < 2; s++)
                wmma::store_matrix_sync(sD + (eg * 4 + r) * 16 * LDD + (jg * 2 + s) * 16,
                                        acc[r][s], LDD, wmma::mem_row_major);
    };

    int it = 0;
    for (int t = blockIdx.x; t < NT_TILES; t += GRID_EDGE, it++) {
        // phase 1: build current tile; overlap epilogue of previous tile
        build(t, it & 1);
        if (it > 0) epilogue((it - 1) & 1);
        __syncthreads();
        // phase 2: tensor GEMM into sD
        gemm();
        __syncthreads();
    }
    if (it > 0) epilogue((it - 1) & 1);
}

// ---------------- final: out = h@W_fc + b ----------------
__global__ void final_kernel(const float* __restrict__ h, const float* __restrict__ W,
                             const float* __restrict__ b, float* __restrict__ out) {
    __shared__ float sh[16][128];
    int n0 = blockIdx.x * 16;
    for (int i = threadIdx.x; i < 16 * 128; i += 128)
        sh[i >> 7][i & 127] = h[n0 * 128 + i];
    __syncthreads();
    int c = threadIdx.x;
    float bc = b[c];
    for (int n = 0; n < 16; n++) {
        float acc = bc;
#pragma unroll 8
        for (int k = 0; k < 128; k++) acc = fmaf(sh[n][k], W[k * 128 + c], acc);
        out[(n0 + n) * 128 + c] = acc;
    }
}

extern "C" void kernel_launch(void* const* d_in, const int* in_sizes, int n_in,
                              void* d_out, int out_size) {
    const float* x    = (const float*)d_in[0];
    const void*  ei   = d_in[1];
    const float* Wemb = (const float*)d_in[2];
    const float* bemb = (const float*)d_in[3];
    const float* W1   = (const float*)d_in[4];
    const float* b1   = (const float*)d_in[5];
    const float* W2   = (const float*)d_in[6];
    const float* b2   = (const float*)d_in[7];
    const float* Wfc  = (const float*)d_in[8];
    const float* bfc  = (const float*)d_in[9];
    float* out = (float*)d_out;

    float *buf0, *buf1, *Ap, *Bp;
    int *es, *ed;
    cudaGetSymbolAddress((void**)&buf0, g_buf0);
    cudaGetSymbolAddress((void**)&buf1, g_buf1);
    cudaGetSymbolAddress((void**)&Ap,   g_A);
    cudaGetSymbolAddress((void**)&Bp,   g_B);
    cudaGetSymbolAddress((void**)&es,   g_es);
    cudaGetSymbolAddress((void**)&ed,   g_ed);

    cudaFuncSetAttribute(edge_persist, cudaFuncAttributeMaxDynamicSharedMemorySize,
                         SMEM_EDGE_BYTES);

    detect_dtype<<<1, 256>>>((const int*)ei);
    zero_cnt<<<(N_NODES + 255) / 256, 256>>>();
    prep_edges<<<(E_TOT + 255) / 256, 256>>>(ei);
    scan_kernel<<<1, 1024>>>();
    scatter_kernel<<<(E_TOT + 255) / 256, 256>>>();
    embed_kernel<<<N_NODES / 16, 128>>>(x, Wemb, bemb, buf0);

    float* hin = buf0;
    float* hout = buf1;
    for (int l = 0; l < NUM_LAYERS; l++) {
        node_transform<<<N_NODES / 16, 256>>>(hin, W1 + l * 2 * H * H, b1 + l * H,
                                              Ap, Bp, hout);
        edge_persist<<<GRID_EDGE, 256, SMEM_EDGE_BYTES>>>(Ap, Bp, W2 + l * H * H,
                                                          b2 + l * H, es, ed, hout);
        float* t = hin; hin = hout; hout = t;
    }
    final_kernel<<<N_NODES / 16, 128>>>(hin, Wfc, bfc, out);
}

// round 8
// speedup vs baseline: 2.2440x; 1.1075x over previous
#include <cuda_runtime.h>
#include <cuda_fp16.h>
#include <mma.h>
#include <cstdint>

using namespace nvcuda;

#define N_NODES 10000
#define N_EDGES 640000
#define E_TOT   (N_EDGES + N_NODES)   // 650000
#define H 128
#define NUM_LAYERS 4

#define TE 128
#define NT_TILES ((E_TOT + TE - 1) / TE)   // 5079
#define GRID_EDGE 148

#define LDW 136   // half elems, W tiles [n][k]
#define LDZ 136   // half elems, Z tiles [e][k]
#define LDD 132   // f32 elems,  D tile  [e][n]

// SMEM byte offsets
#define O_WHI 0u
#define O_WLO 34816u
#define O_Z0  69632u
#define ZBUF_BYTES 34816u                  // 128*LDZ*2, two buffers
#define O_D   139264u
#define O_DST 206848u                      // [2][128] ints
#define O_BIAS 207872u
#define SMEM_EDGE_BYTES 208384u

// ---------------- persistent scratch ----------------
__device__ float g_buf0[N_NODES * H];
__device__ float g_buf1[N_NODES * H];
__device__ float g_A[N_NODES * H];
__device__ float g_B[N_NODES * H];
__device__ int   g_es0[E_TOT];
__device__ int   g_ed0[E_TOT];
__device__ int   g_es[E_TOT];   // sorted by dst
__device__ int   g_ed[E_TOT];   // sorted by dst
__device__ int   g_cnt[N_NODES];
__device__ int   g_pos[N_NODES];
__device__ int   g_is64;

// ---------------- edge dtype detect ----------------
__global__ void detect_dtype(const int* __restrict__ ei32) {
    __shared__ int sbad;
    if (threadIdx.x == 0) sbad = 0;
    __syncthreads();
    int bad = 0;
    for (int i = threadIdx.x; i < 1024; i += 256)
        if (ei32[2 * i + 1] != 0) bad = 1;
    if (bad) atomicOr(&sbad, 1);
    __syncthreads();
    if (threadIdx.x == 0) g_is64 = sbad ? 0 : 1;
}

__global__ void zero_cnt() {
    int i = blockIdx.x * blockDim.x + threadIdx.x;
    if (i < N_NODES) g_cnt[i] = 0;
}

// edge prep + histogram of dst
__global__ void prep_edges(const void* __restrict__ ei) {
    int i = blockIdx.x * blockDim.x + threadIdx.x;
    if (i < N_EDGES) {
        int s, d;
        if (g_is64) {
            const long long* p = (const long long*)ei;
            s = (int)p[i];
            d = (int)p[N_EDGES + i];
        } else {
            const int* p = (const int*)ei;
            s = p[i];
            d = p[N_EDGES + i];
        }
        g_es0[i] = s;
        g_ed0[i] = d;
        atomicAdd(&g_cnt[d], 1);
    } else if (i < E_TOT) {
        int n = i - N_EDGES;
        g_es0[i] = n;
        g_ed0[i] = n;
        atomicAdd(&g_cnt[n], 1);
    }
}

// single-block exclusive scan of g_cnt -> g_pos
__global__ void scan_kernel() {
    __shared__ int part[1024];
    int t = threadIdx.x;
    int s = 0;
    int base = t * 10;
    if (t < 1000) {
#pragma unroll
        for (int i = 0; i < 10; i++) s += g_cnt[base + i];
    }
    part[t] = s;
    __syncthreads();
    for (int off = 1; off < 1024; off <<= 1) {
        int v = part[t];
        if (t >= off) v += part[t - off];
        __syncthreads();
        part[t] = v;
        __syncthreads();
    }
    int excl = (t == 0) ? 0 : part[t - 1];
    if (t < 1000) {
        int run = excl;
#pragma unroll
        for (int i = 0; i < 10; i++) {
            int c = g_cnt[base + i];
            g_pos[base + i] = run;
            run += c;
        }
    }
}

__global__ void scatter_kernel() {
    int i = blockIdx.x * blockDim.x + threadIdx.x;
    if (i < E_TOT) {
        int d = g_ed0[i];
        int p = atomicAdd(&g_pos[d], 1);
        g_es[p] = g_es0[i];
        g_ed[p] = d;
    }
}

// ---------------- embed: h0 = x@W_emb + b ----------------
__global__ void embed_kernel(const float* __restrict__ x, const float* __restrict__ W,
                             const float* __restrict__ b, float* __restrict__ h) {
    __shared__ float sx[16][64];
    int n0 = blockIdx.x * 16;
    for (int i = threadIdx.x; i < 16 * 64; i += 128)
        sx[i >> 6][i & 63] = x[n0 * 64 + i];
    __syncthreads();
    int c = threadIdx.x;
    float bc = b[c];
    for (int n = 0; n < 16; n++) {
        float acc = bc;
#pragma unroll 16
        for (int k = 0; k < 64; k++) acc = fmaf(sx[n][k], W[k * 128 + c], acc);
        h[(n0 + n) * 128 + c] = acc;
    }
}

// ---------------- node transform (256 thr): A = h(W1a-W1b)+b1, B = h W1b ----------------
__global__ void node_transform(const float* __restrict__ h, const float* __restrict__ W1l,
                               const float* __restrict__ b1l, float* __restrict__ A,
                               float* __restrict__ B, float* __restrict__ out_init) {
    __shared__ float sh[16][128];
    int n0 = blockIdx.x * 16;
    for (int i = threadIdx.x; i < 16 * 128; i += 256)
        sh[i >> 7][i & 127] = h[n0 * 128 + i];
    __syncthreads();
    int c = threadIdx.x & 127;
    int nh = (threadIdx.x >> 7) * 8;   // node half: 0 or 8
    float a[8], bb[8];
    float bc = b1l[c];
#pragma unroll
    for (int n = 0; n < 8; n++) { a[n] = bc; bb[n] = 0.f; }
    for (int k = 0; k < 128; k++) {
        float wa = W1l[k * 128 + c];
        float wb = W1l[(k + 128) * 128 + c];
        float wd = wa - wb;
#pragma unroll
        for (int n = 0; n < 8; n++) {
            float hv = sh[nh + n][k];
            a[n]  = fmaf(hv, wd, a[n]);
            bb[n] = fmaf(hv, wb, bb[n]);
        }
    }
#pragma unroll
    for (int n = 0; n < 8; n++) {
        int r = (n0 + nh + n) * 128 + c;
        A[r] = a[n];
        B[r] = bb[n];
        out_init[r] = -3.4028234663852886e38f;
    }
}

// ---------------- persistent edge phase: fp16 2-term, prefetch-overlapped ----------------
__global__ __launch_bounds__(256, 1)
void edge_persist(const float* __restrict__ A, const float* __restrict__ B,
                  const float* __restrict__ W2l, const float* __restrict__ b2l,
                  const int* __restrict__ es, const int* __restrict__ ed,
                  float* __restrict__ hout) {
    extern __shared__ __align__(16) char sm[];
    __half* sWhi = (__half*)(sm + O_WHI);
    __half* sWlo = (__half*)(sm + O_WLO);
    float* sD    = (float*)(sm + O_D);
    int*   sDst  = (int*)(sm + O_DST);     // [2][128]
    float* sBias = (float*)(sm + O_BIAS);

    int tid = threadIdx.x;

    // one-time: W2^T split into fp16 hi/lo: sW[n][k]
    for (int i = tid; i < H * H; i += 256) {
        int k = i >> 7, n = i & 127;
        float w = W2l[i];
        __half hi = __float2half_rn(w);
        __half lo = __float2half_rn(w - __half2float(hi));
        sWhi[n * LDW + k] = hi;
        sWlo[n * LDW + k] = lo;
    }
    if (tid < 128) sBias[tid] = b2l[tid];
    __syncthreads();

    // warp GEMM mapping: 8 warps; jg = w&3 (cols jg*32..+32), eg = w>>2 (edges eg*64..+64)
    int w = tid >> 5;
    int jg = w & 3;
    int eg = w >> 2;

    // build identity: 2 threads per edge
    int e = tid >> 1, q = tid & 1;   // channels [q*64, q*64+64)

    float4 ra[16], rb[16];
    int nd;
    bool vld;

    auto raw_load = [&](int t) {
        int ee = t * TE + e;
        vld = ee < E_TOT;
        int d = vld ? __ldg(&ed[ee]) : 0;
        int s = vld ? __ldg(&es[ee]) : 0;
        nd = vld ? d : -1;
        const float4* pa = (const float4*)(A + (size_t)d * 128 + q * 64);
        const float4* pb = (const float4*)(B + (size_t)s * 128 + q * 64);
#pragma unroll
        for (int i = 0; i < 16; i++) { ra[i] = __ldg(pa + i); rb[i] = __ldg(pb + i); }
    };

    auto cvt_store = [&](int buf) {
        __half* sZ = (__half*)(sm + O_Z0 + (uint32_t)buf * ZBUF_BYTES);
        if (q == 0) sDst[buf * 128 + e] = nd;
#pragma unroll
        for (int i = 0; i < 16; i++) {
            float v0 = 0.f, v1 = 0.f, v2 = 0.f, v3 = 0.f;
            if (vld) {
                v0 = fmaxf(ra[i].x + rb[i].x, 0.f);
                v1 = fmaxf(ra[i].y + rb[i].y, 0.f);
                v2 = fmaxf(ra[i].z + rb[i].z, 0.f);
                v3 = fmaxf(ra[i].w + rb[i].w, 0.f);
            }
            __half2 h01 = __floats2half2_rn(v0, v1);
            __half2 h23 = __floats2half2_rn(v2, v3);
            __half2* p = (__half2*)(sZ + e * LDZ + q * 64 + i * 4);
            p[0] = h01;
            p[1] = h23;
        }
    };

    auto gemm = [&](int buf) {
        const __half* sZ = (const __half*)(sm + O_Z0 + (uint32_t)buf * ZBUF_BYTES);
        wmma::fragment<wmma::accumulator, 16, 16, 16, float> acc[4][2];
#pragma unroll
        for (int r = 0; r < 4; r++)
#pragma unroll
            for (int s = 0; s < 2; s++) wmma::fill_fragment(acc[r][s], 0.f);
#pragma unroll
        for (int k0 = 0; k0 < 8; k0++) {
            wmma::fragment<wmma::matrix_a, 16, 16, 16, __half, wmma::row_major> ah[4];
#pragma unroll
            for (int r = 0; r < 4; r++)
                wmma::load_matrix_sync(ah[r], sZ + (eg * 4 + r) * 16 * LDZ + k0 * 16, LDZ);
#pragma unroll
            for (int s = 0; s < 2; s++) {
                wmma::fragment<wmma::matrix_b, 16, 16, 16, __half, wmma::col_major> bh, bl;
                wmma::load_matrix_sync(bh, sWhi + (jg * 2 + s) * 16 * LDW + k0 * 16, LDW);
                wmma::load_matrix_sync(bl, sWlo + (jg * 2 + s) * 16 * LDW + k0 * 16, LDW);
#pragma unroll
                for (int r = 0; r < 4; r++) {
                    wmma::mma_sync(acc[r][s], ah[r], bh, acc[r][s]);
                    wmma::mma_sync(acc[r][s], ah[r], bl, acc[r][s]);
                }
            }
        }
#pragma unroll
        for (int r = 0; r < 4; r++)
#pragma unroll
            for (int s = 0; s < 2; s++)
                wmma::store_matrix_sync(sD + (eg * 4 + r) * 16 * LDD + (jg * 2 + s) * 16,
                                        acc[r][s], LDD, wmma::mem_row_major);
    };

    // epilogue: 2 halves of 64 edges, segmented atomic max
    auto epilogue = [&](int buf) {
        int c = tid & 127;
        int qq = tid >> 7;          // 0 or 1
        float bias = sBias[c];
        const int* dstb = sDst + buf * 128;
        int cur = dstb[64 * qq];
        float run = -3.4028234663852886e38f;
#pragma unroll 4
        for (int ee = 64 * qq; ee < 64 * qq + 64; ee++) {
            int d = dstb[ee];
            float v = sD[ee * LDD + c] + bias;
            if (d != cur) {
                if (cur >= 0) {
                    float* p = hout + (size_t)cur * 128 + c;
                    if (run >= 0.f) atomicMax((int*)p, __float_as_int(run));
                    else            atomicMin((unsigned int*)p, __float_as_uint(run));
                }
                cur = d;
                run = v;
            } else {
                run = fmaxf(run, v);
            }
        }
        if (cur >= 0) {
            float* p = hout + (size_t)cur * 128 + c;
            if (run >= 0.f) atomicMax((int*)p, __float_as_int(run));
            else            atomicMin((unsigned int*)p, __float_as_uint(run));
        }
    };

    // prologue: build first tile into buf 0
    raw_load(blockIdx.x);
    cvt_store(0);
    __syncthreads();

    int it = 0;
    for (int t = blockIdx.x; t < NT_TILES; t += GRID_EDGE, it++) {
        int p = it & 1;
        int tn = t + GRID_EDGE;
        bool hasNext = tn < NT_TILES;
        if (hasNext) raw_load(tn);     // LDGs in flight across the GEMM
        gemm(p);                        // tensor phase hides gather latency
        if (hasNext) cvt_store(1 - p);  // data arrived long ago
        __syncthreads();
        epilogue(p);
        __syncthreads();
    }
}

// ---------------- final: out = h@W_fc + b ----------------
__global__ void final_kernel(const float* __restrict__ h, const float* __restrict__ W,
                             const float* __restrict__ b, float* __restrict__ out) {
    __shared__ float sh[16][128];
    int n0 = blockIdx.x * 16;
    for (int i = threadIdx.x; i < 16 * 128; i += 128)
        sh[i >> 7][i & 127] = h[n0 * 128 + i];
    __syncthreads();
    int c = threadIdx.x;
    float bc = b[c];
    for (int n = 0; n < 16; n++) {
        float acc = bc;
#pragma unroll 8
        for (int k = 0; k < 128; k++) acc = fmaf(sh[n][k], W[k * 128 + c], acc);
        out[(n0 + n) * 128 + c] = acc;
    }
}

extern "C" void kernel_launch(void* const* d_in, const int* in_sizes, int n_in,
                              void* d_out, int out_size) {
    const float* x    = (const float*)d_in[0];
    const void*  ei   = d_in[1];
    const float* Wemb = (const float*)d_in[2];
    const float* bemb = (const float*)d_in[3];
    const float* W1   = (const float*)d_in[4];
    const float* b1   = (const float*)d_in[5];
    const float* W2   = (const float*)d_in[6];
    const float* b2   = (const float*)d_in[7];
    const float* Wfc  = (const float*)d_in[8];
    const float* bfc  = (const float*)d_in[9];
    float* out = (float*)d_out;

    float *buf0, *buf1, *Ap, *Bp;
    int *es, *ed;
    cudaGetSymbolAddress((void**)&buf0, g_buf0);
    cudaGetSymbolAddress((void**)&buf1, g_buf1);
    cudaGetSymbolAddress((void**)&Ap,   g_A);
    cudaGetSymbolAddress((void**)&Bp,   g_B);
    cudaGetSymbolAddress((void**)&es,   g_es);
    cudaGetSymbolAddress((void**)&ed,   g_ed);

    cudaFuncSetAttribute(edge_persist, cudaFuncAttributeMaxDynamicSharedMemorySize,
                         SMEM_EDGE_BYTES);

    detect_dtype<<<1, 256>>>((const int*)ei);
    zero_cnt<<<(N_NODES + 255) / 256, 256>>>();
    prep_edges<<<(E_TOT + 255) / 256, 256>>>(ei);
    scan_kernel<<<1, 1024>>>();
    scatter_kernel<<<(E_TOT + 255) / 256, 256>>>();
    embed_kernel<<<N_NODES / 16, 128>>>(x, Wemb, bemb, buf0);

    float* hin = buf0;
    float* hout = buf1;
    for (int l = 0; l < NUM_LAYERS; l++) {
        node_transform<<<N_NODES / 16, 256>>>(hin, W1 + l * 2 * H * H, b1 + l * H,
                                              Ap, Bp, hout);
        edge_persist<<<GRID_EDGE, 256, SMEM_EDGE_BYTES>>>(Ap, Bp, W2 + l * H * H,
                                                          b2 + l * H, es, ed, hout);
        float* t = hin; hin = hout; hout = t;
    }
    final_kernel<<<N_NODES / 16, 128>>>(hin, Wfc, bfc, out);
}

// round 10
// speedup vs baseline: 2.2497x; 1.0026x over previous
#include <cuda_runtime.h>
#include <cuda_fp16.h>
#include <cstdint>

#define N_NODES 10000
#define N_EDGES 640000
#define E_TOT   (N_EDGES + N_NODES)   // 650000
#define H 128
#define NUM_LAYERS 4

#define TE 128
#define NT_TILES ((E_TOT + TE - 1) / TE)   // 5079
#define GRID_EDGE 148

#define LDW 136   // half elems, W tiles [n][k]
#define LDZ 136   // half elems, Z tiles [e][k]
#define LDD 132   // f32 elems,  D tile  [e][n]

// SMEM byte offsets
#define O_WHI 0u
#define O_WLO 34816u
#define O_Z0  69632u
#define ZBUF_BYTES 34816u                  // 128*LDZ*2, two buffers
#define O_D   139264u
#define O_DST 206848u                      // [2][128] ints
#define O_BIAS 207872u
#define SMEM_EDGE_BYTES 208384u

// ---------------- persistent scratch ----------------
__device__ float g_buf0[N_NODES * H];
__device__ float g_buf1[N_NODES * H];
__device__ float g_A[N_NODES * H];
__device__ float g_B[N_NODES * H];
__device__ int   g_es0[E_TOT];
__device__ int   g_ed0[E_TOT];
__device__ int   g_es[E_TOT];   // sorted by dst
__device__ int   g_ed[E_TOT];   // sorted by dst
__device__ int   g_cnt[N_NODES];
__device__ int   g_pos[N_NODES];
__device__ int   g_is64;

// ---------------- mma/ldmatrix helpers ----------------
__device__ __forceinline__ void ldsm_x4(uint32_t& r0, uint32_t& r1, uint32_t& r2,
                                        uint32_t& r3, uint32_t addr) {
    asm volatile("ldmatrix.sync.aligned.m8n8.x4.shared.b16 {%0,%1,%2,%3}, [%4];"
                 : "=r"(r0), "=r"(r1), "=r"(r2), "=r"(r3) : "r"(addr));
}
__device__ __forceinline__ void ldsm_x2(uint32_t& r0, uint32_t& r1, uint32_t addr) {
    asm volatile("ldmatrix.sync.aligned.m8n8.x2.shared.b16 {%0,%1}, [%2];"
                 : "=r"(r0), "=r"(r1) : "r"(addr));
}
__device__ __forceinline__ void mma16816(float* d, uint32_t a0, uint32_t a1, uint32_t a2,
                                         uint32_t a3, uint32_t b0, uint32_t b1) {
    asm volatile(
        "mma.sync.aligned.m16n8k16.row.col.f32.f16.f16.f32 "
        "{%0,%1,%2,%3}, {%4,%5,%6,%7}, {%8,%9}, {%0,%1,%2,%3};"
        : "+f"(d[0]), "+f"(d[1]), "+f"(d[2]), "+f"(d[3])
        : "r"(a0), "r"(a1), "r"(a2), "r"(a3), "r"(b0), "r"(b1));
}

// ---------------- edge dtype detect ----------------
__global__ void detect_dtype(const int* __restrict__ ei32) {
    __shared__ int sbad;
    if (threadIdx.x == 0) sbad = 0;
    __syncthreads();
    int bad = 0;
    for (int i = threadIdx.x; i < 1024; i += 256)
        if (ei32[2 * i + 1] != 0) bad = 1;
    if (bad) atomicOr(&sbad, 1);
    __syncthreads();
    if (threadIdx.x == 0) g_is64 = sbad ? 0 : 1;
}

__global__ void zero_cnt() {
    int i = blockIdx.x * blockDim.x + threadIdx.x;
    if (i < N_NODES) g_cnt[i] = 0;
}

// edge prep + histogram of dst
__global__ void prep_edges(const void* __restrict__ ei) {
    int i = blockIdx.x * blockDim.x + threadIdx.x;
    if (i < N_EDGES) {
        int s, d;
        if (g_is64) {
            const long long* p = (const long long*)ei;
            s = (int)p[i];
            d = (int)p[N_EDGES + i];
        } else {
            const int* p = (const int*)ei;
            s = p[i];
            d = p[N_EDGES + i];
        }
        g_es0[i] = s;
        g_ed0[i] = d;
        atomicAdd(&g_cnt[d], 1);
    } else if (i < E_TOT) {
        int n = i - N_EDGES;
        g_es0[i] = n;
        g_ed0[i] = n;
        atomicAdd(&g_cnt[n], 1);
    }
}

// single-block exclusive scan of g_cnt -> g_pos
__global__ void scan_kernel() {
    __shared__ int part[1024];
    int t = threadIdx.x;
    int s = 0;
    int base = t * 10;
    if (t < 1000) {
#pragma unroll
        for (int i = 0; i < 10; i++) s += g_cnt[base + i];
    }
    part[t] = s;
    __syncthreads();
    for (int off = 1; off < 1024; off <<= 1) {
        int v = part[t];
        if (t >= off) v += part[t - off];
        __syncthreads();
        part[t] = v;
        __syncthreads();
    }
    int excl = (t == 0) ? 0 : part[t - 1];
    if (t < 1000) {
        int run = excl;
#pragma unroll
        for (int i = 0; i < 10; i++) {
            int c = g_cnt[base + i];
            g_pos[base + i] = run;
            run += c;
        }
    }
}

__global__ void scatter_kernel() {
    int i = blockIdx.x * blockDim.x + threadIdx.x;
    if (i < E_TOT) {
        int d = g_ed0[i];
        int p = atomicAdd(&g_pos[d], 1);
        g_es[p] = g_es0[i];
        g_ed[p] = d;
    }
}

// ---------------- embed: h0 = x@W_emb + b ----------------
__global__ void embed_kernel(const float* __restrict__ x, const float* __restrict__ W,
                             const float* __restrict__ b, float* __restrict__ h) {
    __shared__ float sx[16][64];
    int n0 = blockIdx.x * 16;
    for (int i = threadIdx.x; i < 16 * 64; i += 128)
        sx[i >> 6][i & 63] = x[n0 * 64 + i];
    __syncthreads();
    int c = threadIdx.x;
    float bc = b[c];
    for (int n = 0; n < 16; n++) {
        float acc = bc;
#pragma unroll 16
        for (int k = 0; k < 64; k++) acc = fmaf(sx[n][k], W[k * 128 + c], acc);
        h[(n0 + n) * 128 + c] = acc;
    }
}

// ---------------- node transform (256 thr): A = h(W1a-W1b)+b1, B = h W1b ----------------
__global__ void node_transform(const float* __restrict__ h, const float* __restrict__ W1l,
                               const float* __restrict__ b1l, float* __restrict__ A,
                               float* __restrict__ B, float* __restrict__ out_init) {
    __shared__ float sh[16][128];
    int n0 = blockIdx.x * 16;
    for (int i = threadIdx.x; i < 16 * 128; i += 256)
        sh[i >> 7][i & 127] = h[n0 * 128 + i];
    __syncthreads();
    int c = threadIdx.x & 127;
    int nh = (threadIdx.x >> 7) * 8;   // node half: 0 or 8
    float a[8], bb[8];
    float bc = b1l[c];
#pragma unroll
    for (int n = 0; n < 8; n++) { a[n] = bc; bb[n] = 0.f; }
    for (int k = 0; k < 128; k++) {
        float wa = W1l[k * 128 + c];
        float wb = W1l[(k + 128) * 128 + c];
        float wd = wa - wb;
#pragma unroll
        for (int n = 0; n < 8; n++) {
            float hv = sh[nh + n][k];
            a[n]  = fmaf(hv, wd, a[n]);
            bb[n] = fmaf(hv, wb, bb[n]);
        }
    }
#pragma unroll
    for (int n = 0; n < 8; n++) {
        int r = (n0 + nh + n) * 128 + c;
        A[r] = a[n];
        B[r] = bb[n];
        out_init[r] = -3.4028234663852886e38f;
    }
}

// ---------------- persistent edge phase: mma.sync fp16 2-term ----------------
__global__ __launch_bounds__(256, 1)
void edge_persist(const float* __restrict__ A, const float* __restrict__ B,
                  const float* __restrict__ W2l, const float* __restrict__ b2l,
                  const int* __restrict__ es, const int* __restrict__ ed,
                  float* __restrict__ hout) {
    extern __shared__ __align__(16) char sm[];
    __half* sWhi = (__half*)(sm + O_WHI);
    __half* sWlo = (__half*)(sm + O_WLO);
    float* sD    = (float*)(sm + O_D);
    int*   sDst  = (int*)(sm + O_DST);     // [2][128]
    float* sBias = (float*)(sm + O_BIAS);

    int tid = threadIdx.x;
    int lane = tid & 31;
    int w = tid >> 5;

    uint32_t smb = (uint32_t)__cvta_generic_to_shared(sm);

    // one-time: W2^T split into fp16 hi/lo: sW[n][k]
    for (int i = tid; i < H * H; i += 256) {
        int k = i >> 7, n = i & 127;
        float wv = W2l[i];
        __half hi = __float2half_rn(wv);
        __half lo = __float2half_rn(wv - __half2float(hi));
        sWhi[n * LDW + k] = hi;
        sWlo[n * LDW + k] = lo;
    }
    if (tid < 128) sBias[tid] = b2l[tid];
    __syncthreads();

    // GEMM mapping: 8 warps; er = w>>1 edges [er*32,+32); nc = w&1 cols [nc*64,+64)
    int er = w >> 1;
    int nc = w & 1;
    int g  = lane >> 2;
    int t2 = (lane & 3) * 2;

    // precomputed ldmatrix lane addresses (byte offsets from smem base)
    // A: lanes 0-15 -> rows (lane&15), k-half (lane>>4)
    uint32_t aoff0 = ((uint32_t)((er * 32 + (lane & 15)) * LDZ + (lane >> 4) * 8)) * 2u;
    uint32_t aoff1 = aoff0 + 16u * LDZ * 2u;   // second m-frag (+16 rows)
    // B: lanes 0-15 -> n row n0+(lane&7), k-half ((lane>>3)&1)
    int bl = lane & 15;
    uint32_t brow = (uint32_t)(nc * 64 + (bl & 7));
    uint32_t bkh  = (uint32_t)((bl >> 3) & 1) * 8u;
    uint32_t bhioff = smb + O_WHI + (brow * LDW + bkh) * 2u;
    uint32_t blooff = smb + O_WLO + (brow * LDW + bkh) * 2u;

    // build identity: 2 threads per edge
    int e = tid >> 1, q = tid & 1;   // channels [q*64, q*64+64)

    float4 ra[16], rb[16];
    int nd;
    bool vld;

    auto raw_load = [&](int t) {
        int ee = t * TE + e;
        vld = ee < E_TOT;
        int d = vld ? __ldg(&ed[ee]) : 0;
        int s = vld ? __ldg(&es[ee]) : 0;
        nd = vld ? d : -1;
        const float4* pa = (const float4*)(A + (size_t)d * 128 + q * 64);
        const float4* pb = (const float4*)(B + (size_t)s * 128 + q * 64);
#pragma unroll
        for (int i = 0; i < 16; i++) { ra[i] = __ldg(pa + i); rb[i] = __ldg(pb + i); }
    };

    auto cvt_store = [&](int buf) {
        __half* sZ = (__half*)(sm + O_Z0 + (uint32_t)buf * ZBUF_BYTES);
        if (q == 0) sDst[buf * 128 + e] = nd;
#pragma unroll
        for (int i = 0; i < 16; i++) {
            float v0 = 0.f, v1 = 0.f, v2 = 0.f, v3 = 0.f;
            if (vld) {
                v0 = fmaxf(ra[i].x + rb[i].x, 0.f);
                v1 = fmaxf(ra[i].y + rb[i].y, 0.f);
                v2 = fmaxf(ra[i].z + rb[i].z, 0.f);
                v3 = fmaxf(ra[i].w + rb[i].w, 0.f);
            }
            __half2* p = (__half2*)(sZ + e * LDZ + q * 64 + i * 4);
            p[0] = __floats2half2_rn(v0, v1);
            p[1] = __floats2half2_rn(v2, v3);
        }
    };

    auto gemm = [&](int buf) {
        uint32_t zbase = smb + O_Z0 + (uint32_t)buf * ZBUF_BYTES;
        float acc[2][8][4];
#pragma unroll
        for (int f = 0; f < 2; f++)
#pragma unroll
            for (int j = 0; j < 8; j++)
#pragma unroll
                for (int r = 0; r < 4; r++) acc[f][j][r] = 0.f;

#pragma unroll
        for (int k0 = 0; k0 < 8; k0++) {
            uint32_t a0[4], a1[4];
            ldsm_x4(a0[0], a0[1], a0[2], a0[3], zbase + aoff0 + (uint32_t)k0 * 32u);
            ldsm_x4(a1[0], a1[1], a1[2], a1[3], zbase + aoff1 + (uint32_t)k0 * 32u);
#pragma unroll
            for (int j = 0; j < 8; j++) {
                uint32_t jb = (uint32_t)(j * 8 * LDW * 2) + (uint32_t)k0 * 32u;
                uint32_t bh0, bh1, bl0, bl1;
                ldsm_x2(bh0, bh1, bhioff + jb);
                ldsm_x2(bl0, bl1, blooff + jb);
                mma16816(acc[0][j], a0[0], a0[1], a0[2], a0[3], bh0, bh1);
                mma16816(acc[0][j], a0[0], a0[1], a0[2], a0[3], bl0, bl1);
                mma16816(acc[1][j], a1[0], a1[1], a1[2], a1[3], bh0, bh1);
                mma16816(acc[1][j], a1[0], a1[1], a1[2], a1[3], bl0, bl1);
            }
        }
        // store D: documented m16n8k16 C layout
#pragma unroll
        for (int f = 0; f < 2; f++) {
            int r0 = er * 32 + f * 16 + g;
#pragma unroll
            for (int j = 0; j < 8; j++) {
                int c = nc * 64 + j * 8 + t2;
                *(float2*)(sD + r0 * LDD + c)       = make_float2(acc[f][j][0], acc[f][j][1]);
                *(float2*)(sD + (r0 + 8) * LDD + c) = make_float2(acc[f][j][2], acc[f][j][3]);
            }
        }
    };

    // epilogue: 2 halves of 64 edges, segmented atomic max
    auto epilogue = [&](int buf) {
        int c = tid & 127;
        int qq = tid >> 7;
        float bias = sBias[c];
        const int* dstb = sDst + buf * 128;
        int cur = dstb[64 * qq];
        float run = -3.4028234663852886e38f;
#pragma unroll 4
        for (int ee = 64 * qq; ee < 64 * qq + 64; ee++) {
            int d = dstb[ee];
            float v = sD[ee * LDD + c] + bias;
            if (d != cur) {
                if (cur >= 0) {
                    float* p = hout + (size_t)cur * 128 + c;
                    if (run >= 0.f) atomicMax((int*)p, __float_as_int(run));
                    else            atomicMin((unsigned int*)p, __float_as_uint(run));
                }
                cur = d;
                run = v;
            } else {
                run = fmaxf(run, v);
            }
        }
        if (cur >= 0) {
            float* p = hout + (size_t)cur * 128 + c;
            if (run >= 0.f) atomicMax((int*)p, __float_as_int(run));
            else            atomicMin((unsigned int*)p, __float_as_uint(run));
        }
    };

    // prologue
    raw_load(blockIdx.x);
    cvt_store(0);
    __syncthreads();

    int it = 0;
    for (int t = blockIdx.x; t < NT_TILES; t += GRID_EDGE, it++) {
        int p = it & 1;
        gemm(p);                        // acc regs live only here
        __syncthreads();                // sD visible, Z[p] free
        int tn = t + GRID_EDGE;
        bool hasNext = tn < NT_TILES;
        if (hasNext) raw_load(tn);      // LDGs in flight...
        epilogue(p);                    // ...hidden behind epilogue work
        if (hasNext) cvt_store(1 - p);
        __syncthreads();
    }
}

// ---------------- final: out = h@W_fc + b ----------------
__global__ void final_kernel(const float* __restrict__ h, const float* __restrict__ W,
                             const float* __restrict__ b, float* __restrict__ out) {
    __shared__ float sh[16][128];
    int n0 = blockIdx.x * 16;
    for (int i = threadIdx.x; i < 16 * 128; i += 128)
        sh[i >> 7][i & 127] = h[n0 * 128 + i];
    __syncthreads();
    int c = threadIdx.x;
    float bc = b[c];
    for (int n = 0; n < 16; n++) {
        float acc = bc;
#pragma unroll 8
        for (int k = 0; k < 128; k++) acc = fmaf(sh[n][k], W[k * 128 + c], acc);
        out[(n0 + n) * 128 + c] = acc;
    }
}

extern "C" void kernel_launch(void* const* d_in, const int* in_sizes, int n_in,
                              void* d_out, int out_size) {
    const float* x    = (const float*)d_in[0];
    const void*  ei   = d_in[1];
    const float* Wemb = (const float*)d_in[2];
    const float* bemb = (const float*)d_in[3];
    const float* W1   = (const float*)d_in[4];
    const float* b1   = (const float*)d_in[5];
    const float* W2   = (const float*)d_in[6];
    const float* b2   = (const float*)d_in[7];
    const float* Wfc  = (const float*)d_in[8];
    const float* bfc  = (const float*)d_in[9];
    float* out = (float*)d_out;

    float *buf0, *buf1, *Ap, *Bp;
    int *es, *ed;
    cudaGetSymbolAddress((void**)&buf0, g_buf0);
    cudaGetSymbolAddress((void**)&buf1, g_buf1);
    cudaGetSymbolAddress((void**)&Ap,   g_A);
    cudaGetSymbolAddress((void**)&Bp,   g_B);
    cudaGetSymbolAddress((void**)&es,   g_es);
    cudaGetSymbolAddress((void**)&ed,   g_ed);

    cudaFuncSetAttribute(edge_persist, cudaFuncAttributeMaxDynamicSharedMemorySize,
                         SMEM_EDGE_BYTES);

    detect_dtype<<<1, 256>>>((const int*)ei);
    zero_cnt<<<(N_NODES + 255) / 256, 256>>>();
    prep_edges<<<(E_TOT + 255) / 256, 256>>>(ei);
    scan_kernel<<<1, 1024>>>();
    scatter_kernel<<<(E_TOT + 255) / 256, 256>>>();
    embed_kernel<<<N_NODES / 16, 128>>>(x, Wemb, bemb, buf0);

    float* hin = buf0;
    float* hout = buf1;
    for (int l = 0; l < NUM_LAYERS; l++) {
        node_transform<<<N_NODES / 16, 256>>>(hin, W1 + l * 2 * H * H, b1 + l * H,
                                              Ap, Bp, hout);
        edge_persist<<<GRID_EDGE, 256, SMEM_EDGE_BYTES>>>(Ap, Bp, W2 + l * H * H,
                                                          b2 + l * H, es, ed, hout);
        float* t = hin; hin = hout; hout = t;
    }
    final_kernel<<<N_NODES / 16, 128>>>(hin, Wfc, bfc, out);
}

// round 11
// speedup vs baseline: 3.3401x; 1.4847x over previous
#include <cuda_runtime.h>
#include <cuda_fp16.h>
#include <cstdint>

#define N_NODES 10000
#define N_EDGES 640000
#define E_TOT   (N_EDGES + N_NODES)   // 650000
#define H 128
#define NUM_LAYERS 4

#define TE 128
#define NT_TILES ((E_TOT + TE - 1) / TE)   // 5079
#define GRID_EDGE 148

#define LDW 136   // half elems, W tile [n][k]
#define LDZ 136   // half elems, Z tiles [e][k]
#define LDD 132   // f32 elems,  D tile  [e][n]

// SMEM byte offsets (compacted, single-precision-W layout)
#define O_W   0u
#define O_Z0  34816u
#define ZBUF_BYTES 34816u                  // 128*LDZ*2, two buffers
#define O_D   104448u
#define O_DST 172032u                      // [2][128] ints
#define O_BIAS 173056u
#define SMEM_EDGE_BYTES 173568u

// ---------------- persistent scratch ----------------
__device__ float g_buf0[N_NODES * H];
__device__ float g_buf1[N_NODES * H];
__device__ float g_A[N_NODES * H];
__device__ float g_B[N_NODES * H];
__device__ int   g_es0[E_TOT];
__device__ int   g_ed0[E_TOT];
__device__ int   g_es[E_TOT];   // sorted by dst
__device__ int   g_ed[E_TOT];   // sorted by dst
__device__ int   g_cnt[N_NODES];
__device__ int   g_pos[N_NODES];
__device__ int   g_is64;

// ---------------- mma/ldmatrix helpers ----------------
__device__ __forceinline__ void ldsm_x4(uint32_t& r0, uint32_t& r1, uint32_t& r2,
                                        uint32_t& r3, uint32_t addr) {
    asm volatile("ldmatrix.sync.aligned.m8n8.x4.shared.b16 {%0,%1,%2,%3}, [%4];"
                 : "=r"(r0), "=r"(r1), "=r"(r2), "=r"(r3) : "r"(addr));
}
__device__ __forceinline__ void ldsm_x2(uint32_t& r0, uint32_t& r1, uint32_t addr) {
    asm volatile("ldmatrix.sync.aligned.m8n8.x2.shared.b16 {%0,%1}, [%2];"
                 : "=r"(r0), "=r"(r1) : "r"(addr));
}
__device__ __forceinline__ void mma16816(float* d, uint32_t a0, uint32_t a1, uint32_t a2,
                                         uint32_t a3, uint32_t b0, uint32_t b1) {
    asm volatile(
        "mma.sync.aligned.m16n8k16.row.col.f32.f16.f16.f32 "
        "{%0,%1,%2,%3}, {%4,%5,%6,%7}, {%8,%9}, {%0,%1,%2,%3};"
        : "+f"(d[0]), "+f"(d[1]), "+f"(d[2]), "+f"(d[3])
        : "r"(a0), "r"(a1), "r"(a2), "r"(a3), "r"(b0), "r"(b1));
}

// ---------------- edge dtype detect ----------------
__global__ void detect_dtype(const int* __restrict__ ei32) {
    __shared__ int sbad;
    if (threadIdx.x == 0) sbad = 0;
    __syncthreads();
    int bad = 0;
    for (int i = threadIdx.x; i < 1024; i += 256)
        if (ei32[2 * i + 1] != 0) bad = 1;
    if (bad) atomicOr(&sbad, 1);
    __syncthreads();
    if (threadIdx.x == 0) g_is64 = sbad ? 0 : 1;
}

__global__ void zero_cnt() {
    int i = blockIdx.x * blockDim.x + threadIdx.x;
    if (i < N_NODES) g_cnt[i] = 0;
}

// edge prep + histogram of dst
__global__ void prep_edges(const void* __restrict__ ei) {
    int i = blockIdx.x * blockDim.x + threadIdx.x;
    if (i < N_EDGES) {
        int s, d;
        if (g_is64) {
            const long long* p = (const long long*)ei;
            s = (int)p[i];
            d = (int)p[N_EDGES + i];
        } else {
            const int* p = (const int*)ei;
            s = p[i];
            d = p[N_EDGES + i];
        }
        g_es0[i] = s;
        g_ed0[i] = d;
        atomicAdd(&g_cnt[d], 1);
    } else if (i < E_TOT) {
        int n = i - N_EDGES;
        g_es0[i] = n;
        g_ed0[i] = n;
        atomicAdd(&g_cnt[n], 1);
    }
}

// single-block exclusive scan of g_cnt -> g_pos
__global__ void scan_kernel() {
    __shared__ int part[1024];
    int t = threadIdx.x;
    int s = 0;
    int base = t * 10;
    if (t < 1000) {
#pragma unroll
        for (int i = 0; i < 10; i++) s += g_cnt[base + i];
    }
    part[t] = s;
    __syncthreads();
    for (int off = 1; off < 1024; off <<= 1) {
        int v = part[t];
        if (t >= off) v += part[t - off];
        __syncthreads();
        part[t] = v;
        __syncthreads();
    }
    int excl = (t == 0) ? 0 : part[t - 1];
    if (t < 1000) {
        int run = excl;
#pragma unroll
        for (int i = 0; i < 10; i++) {
            int c = g_cnt[base + i];
            g_pos[base + i] = run;
            run += c;
        }
    }
}

__global__ void scatter_kernel() {
    int i = blockIdx.x * blockDim.x + threadIdx.x;
    if (i < E_TOT) {
        int d = g_ed0[i];
        int p = atomicAdd(&g_pos[d], 1);
        g_es[p] = g_es0[i];
        g_ed[p] = d;
    }
}

// ---------------- embed: h0 = x@W_emb + b ----------------
__global__ void embed_kernel(const float* __restrict__ x, const float* __restrict__ W,
                             const float* __restrict__ b, float* __restrict__ h) {
    __shared__ float sx[16][64];
    int n0 = blockIdx.x * 16;
    for (int i = threadIdx.x; i < 16 * 64; i += 128)
        sx[i >> 6][i & 63] = x[n0 * 64 + i];
    __syncthreads();
    int c = threadIdx.x;
    float bc = b[c];
    for (int n = 0; n < 16; n++) {
        float acc = bc;
#pragma unroll 16
        for (int k = 0; k < 64; k++) acc = fmaf(sx[n][k], W[k * 128 + c], acc);
        h[(n0 + n) * 128 + c] = acc;
    }
}

// ---------------- node transform (256 thr): A = h(W1a-W1b)+b1, B = h W1b ----------------
__global__ void node_transform(const float* __restrict__ h, const float* __restrict__ W1l,
                               const float* __restrict__ b1l, float* __restrict__ A,
                               float* __restrict__ B, float* __restrict__ out_init) {
    __shared__ float sh[16][128];
    int n0 = blockIdx.x * 16;
    for (int i = threadIdx.x; i < 16 * 128; i += 256)
        sh[i >> 7][i & 127] = h[n0 * 128 + i];
    __syncthreads();
    int c = threadIdx.x & 127;
    int nh = (threadIdx.x >> 7) * 8;   // node half: 0 or 8
    float a[8], bb[8];
    float bc = b1l[c];
#pragma unroll
    for (int n = 0; n < 8; n++) { a[n] = bc; bb[n] = 0.f; }
    for (int k = 0; k < 128; k++) {
        float wa = W1l[k * 128 + c];
        float wb = W1l[(k + 128) * 128 + c];
        float wd = wa - wb;
#pragma unroll
        for (int n = 0; n < 8; n++) {
            float hv = sh[nh + n][k];
            a[n]  = fmaf(hv, wd, a[n]);
            bb[n] = fmaf(hv, wb, bb[n]);
        }
    }
#pragma unroll
    for (int n = 0; n < 8; n++) {
        int r = (n0 + nh + n) * 128 + c;
        A[r] = a[n];
        B[r] = bb[n];
        out_init[r] = -3.4028234663852886e38f;
    }
}

// ---------------- persistent edge phase: mma.sync fp16 single-W ----------------
__global__ __launch_bounds__(256, 1)
void edge_persist(const float* __restrict__ A, const float* __restrict__ B,
                  const float* __restrict__ W2l, const float* __restrict__ b2l,
                  const int* __restrict__ es, const int* __restrict__ ed,
                  float* __restrict__ hout) {
    extern __shared__ __align__(16) char sm[];
    __half* sW   = (__half*)(sm + O_W);
    float* sD    = (float*)(sm + O_D);
    int*   sDst  = (int*)(sm + O_DST);     // [2][128]
    float* sBias = (float*)(sm + O_BIAS);

    int tid = threadIdx.x;
    int lane = tid & 31;
    int w = tid >> 5;

    uint32_t smb = (uint32_t)__cvta_generic_to_shared(sm);

    // one-time: W2^T into fp16: sW[n][k]
    for (int i = tid; i < H * H; i += 256) {
        int k = i >> 7, n = i & 127;
        sW[n * LDW + k] = __float2half_rn(W2l[i]);
    }
    if (tid < 128) sBias[tid] = b2l[tid];
    __syncthreads();

    // GEMM mapping: 8 warps; er = w>>1 edges [er*32,+32); nc = w&1 cols [nc*64,+64)
    int er = w >> 1;
    int nc = w & 1;
    int g  = lane >> 2;
    int t2 = (lane & 3) * 2;

    // ldmatrix lane addresses
    uint32_t aoff0 = ((uint32_t)((er * 32 + (lane & 15)) * LDZ + (lane >> 4) * 8)) * 2u;
    uint32_t aoff1 = aoff0 + 16u * LDZ * 2u;
    int bl = lane & 15;
    uint32_t brow = (uint32_t)(nc * 64 + (bl & 7));
    uint32_t bkh  = (uint32_t)((bl >> 3) & 1) * 8u;
    uint32_t bwoff = smb + O_W + (brow * LDW + bkh) * 2u;

    // build identity: 2 threads per edge
    int e = tid >> 1, q = tid & 1;   // channels [q*64, q*64+64)

    float4 ra[16], rb[16];
    int nd;
    bool vld;

    auto raw_load = [&](int t) {
        int ee = t * TE + e;
        vld = ee < E_TOT;
        int d = vld ? __ldg(&ed[ee]) : 0;
        int s = vld ? __ldg(&es[ee]) : 0;
        nd = vld ? d : -1;
        const float4* pa = (const float4*)(A + (size_t)d * 128 + q * 64);
        const float4* pb = (const float4*)(B + (size_t)s * 128 + q * 64);
#pragma unroll
        for (int i = 0; i < 16; i++) { ra[i] = __ldg(pa + i); rb[i] = __ldg(pb + i); }
    };

    auto cvt_store = [&](int buf) {
        __half* sZ = (__half*)(sm + O_Z0 + (uint32_t)buf * ZBUF_BYTES);
        if (q == 0) sDst[buf * 128 + e] = nd;
#pragma unroll
        for (int i = 0; i < 8; i++) {
            float4 a0 = ra[2 * i], a1 = ra[2 * i + 1];
            float4 b0 = rb[2 * i], b1 = rb[2 * i + 1];
            float v0 = 0.f, v1 = 0.f, v2 = 0.f, v3 = 0.f;
            float v4 = 0.f, v5 = 0.f, v6 = 0.f, v7 = 0.f;
            if (vld) {
                v0 = fmaxf(a0.x + b0.x, 0.f);
                v1 = fmaxf(a0.y + b0.y, 0.f);
                v2 = fmaxf(a0.z + b0.z, 0.f);
                v3 = fmaxf(a0.w + b0.w, 0.f);
                v4 = fmaxf(a1.x + b1.x, 0.f);
                v5 = fmaxf(a1.y + b1.y, 0.f);
                v6 = fmaxf(a1.z + b1.z, 0.f);
                v7 = fmaxf(a1.w + b1.w, 0.f);
            }
            __half2 h0 = __floats2half2_rn(v0, v1);
            __half2 h1 = __floats2half2_rn(v2, v3);
            __half2 h2 = __floats2half2_rn(v4, v5);
            __half2 h3 = __floats2half2_rn(v6, v7);
            uint4 pk;
            pk.x = *(uint32_t*)&h0;
            pk.y = *(uint32_t*)&h1;
            pk.z = *(uint32_t*)&h2;
            pk.w = *(uint32_t*)&h3;
            *(uint4*)(sZ + e * LDZ + q * 64 + i * 8) = pk;   // 16B aligned: 272|128|16
        }
    };

    auto gemm = [&](int buf) {
        uint32_t zbase = smb + O_Z0 + (uint32_t)buf * ZBUF_BYTES;
        float acc[2][8][4];
#pragma unroll
        for (int f = 0; f < 2; f++)
#pragma unroll
            for (int j = 0; j < 8; j++)
#pragma unroll
                for (int r = 0; r < 4; r++) acc[f][j][r] = 0.f;

#pragma unroll
        for (int k0 = 0; k0 < 8; k0++) {
            uint32_t a0[4], a1[4];
            ldsm_x4(a0[0], a0[1], a0[2], a0[3], zbase + aoff0 + (uint32_t)k0 * 32u);
            ldsm_x4(a1[0], a1[1], a1[2], a1[3], zbase + aoff1 + (uint32_t)k0 * 32u);
#pragma unroll
            for (int j = 0; j < 8; j++) {
                uint32_t jb = (uint32_t)(j * 8 * LDW * 2) + (uint32_t)k0 * 32u;
                uint32_t b0, b1;
                ldsm_x2(b0, b1, bwoff + jb);
                mma16816(acc[0][j], a0[0], a0[1], a0[2], a0[3], b0, b1);
                mma16816(acc[1][j], a1[0], a1[1], a1[2], a1[3], b0, b1);
            }
        }
#pragma unroll
        for (int f = 0; f < 2; f++) {
            int r0 = er * 32 + f * 16 + g;
#pragma unroll
            for (int j = 0; j < 8; j++) {
                int c = nc * 64 + j * 8 + t2;
                *(float2*)(sD + r0 * LDD + c)       = make_float2(acc[f][j][0], acc[f][j][1]);
                *(float2*)(sD + (r0 + 8) * LDD + c) = make_float2(acc[f][j][2], acc[f][j][3]);
            }
        }
    };

    // epilogue: 4 quarters of 32 edges, 2 channels per thread, segmented atomic max
    auto epilogue = [&](int buf) {
        int cp = tid & 63;          // channel pair, c = 2*cp
        int qq = tid >> 6;          // 0..3
        float2 bias2 = *(float2*)(sBias + cp * 2);
        const int* dstb = sDst + buf * 128;
        int cur = dstb[32 * qq];
        float r0 = -3.4028234663852886e38f, r1 = -3.4028234663852886e38f;
#pragma unroll 4
        for (int ee = 32 * qq; ee < 32 * qq + 32; ee++) {
            int d = dstb[ee];
            float2 v = *(float2*)(sD + ee * LDD + cp * 2);
            v.x += bias2.x;
            v.y += bias2.y;
            if (d != cur) {
                if (cur >= 0) {
                    float* p = hout + (size_t)cur * 128 + cp * 2;
                    if (r0 >= 0.f) atomicMax((int*)p, __float_as_int(r0));
                    else           atomicMin((unsigned int*)p, __float_as_uint(r0));
                    if (r1 >= 0.f) atomicMax((int*)(p + 1), __float_as_int(r1));
                    else           atomicMin((unsigned int*)(p + 1), __float_as_uint(r1));
                }
                cur = d;
                r0 = v.x;
                r1 = v.y;
            } else {
                r0 = fmaxf(r0, v.x);
                r1 = fmaxf(r1, v.y);
            }
        }
        if (cur >= 0) {
            float* p = hout + (size_t)cur * 128 + cp * 2;
            if (r0 >= 0.f) atomicMax((int*)p, __float_as_int(r0));
            else           atomicMin((unsigned int*)p, __float_as_uint(r0));
            if (r1 >= 0.f) atomicMax((int*)(p + 1), __float_as_int(r1));
            else           atomicMin((unsigned int*)(p + 1), __float_as_uint(r1));
        }
    };

    // prologue
    raw_load(blockIdx.x);
    cvt_store(0);
    __syncthreads();

    int it = 0;
    for (int t = blockIdx.x; t < NT_TILES; t += GRID_EDGE, it++) {
        int p = it & 1;
        gemm(p);                        // acc regs live only here
        __syncthreads();                // sD visible, Z[p] free
        int tn = t + GRID_EDGE;
        bool hasNext = tn < NT_TILES;
        if (hasNext) raw_load(tn);      // LDGs in flight...
        epilogue(p);                    // ...hidden behind epilogue work
        if (hasNext) cvt_store(1 - p);
        __syncthreads();
    }
}

// ---------------- final: out = h@W_fc + b ----------------
__global__ void final_kernel(const float* __restrict__ h, const float* __restrict__ W,
                             const float* __restrict__ b, float* __restrict__ out) {
    __shared__ float sh[16][128];
    int n0 = blockIdx.x * 16;
    for (int i = threadIdx.x; i < 16 * 128; i += 128)
        sh[i >> 7][i & 127] = h[n0 * 128 + i];
    __syncthreads();
    int c = threadIdx.x;
    float bc = b[c];
    for (int n = 0; n < 16; n++) {
        float acc = bc;
#pragma unroll 8
        for (int k = 0; k < 128; k++) acc = fmaf(sh[n][k], W[k * 128 + c], acc);
        out[(n0 + n) * 128 + c] = acc;
    }
}

extern "C" void kernel_launch(void* const* d_in, const int* in_sizes, int n_in,
                              void* d_out, int out_size) {
    const float* x    = (const float*)d_in[0];
    const void*  ei   = d_in[1];
    const float* Wemb = (const float*)d_in[2];
    const float* bemb = (const float*)d_in[3];
    const float* W1   = (const float*)d_in[4];
    const float* b1   = (const float*)d_in[5];
    const float* W2   = (const float*)d_in[6];
    const float* b2   = (const float*)d_in[7];
    const float* Wfc  = (const float*)d_in[8];
    const float* bfc  = (const float*)d_in[9];
    float* out = (float*)d_out;

    float *buf0, *buf1, *Ap, *Bp;
    int *es, *ed;
    cudaGetSymbolAddress((void**)&buf0, g_buf0);
    cudaGetSymbolAddress((void**)&buf1, g_buf1);
    cudaGetSymbolAddress((void**)&Ap,   g_A);
    cudaGetSymbolAddress((void**)&Bp,   g_B);
    cudaGetSymbolAddress((void**)&es,   g_es);
    cudaGetSymbolAddress((void**)&ed,   g_ed);

    cudaFuncSetAttribute(edge_persist, cudaFuncAttributeMaxDynamicSharedMemorySize,
                         SMEM_EDGE_BYTES);

    detect_dtype<<<1, 256>>>((const int*)ei);
    zero_cnt<<<(N_NODES + 255) / 256, 256>>>();
    prep_edges<<<(E_TOT + 255) / 256, 256>>>(ei);
    scan_kernel<<<1, 1024>>>();
    scatter_kernel<<<(E_TOT + 255) / 256, 256>>>();
    embed_kernel<<<N_NODES / 16, 128>>>(x, Wemb, bemb, buf0);

    float* hin = buf0;
    float* hout = buf1;
    for (int l = 0; l < NUM_LAYERS; l++) {
        node_transform<<<N_NODES / 16, 256>>>(hin, W1 + l * 2 * H * H, b1 + l * H,
                                              Ap, Bp, hout);
        edge_persist<<<GRID_EDGE, 256, SMEM_EDGE_BYTES>>>(Ap, Bp, W2 + l * H * H,
                                                          b2 + l * H, es, ed, hout);
        float* t = hin; hin = hout; hout = t;
    }
    final_kernel<<<N_NODES / 16, 128>>>(hin, Wfc, bfc, out);
}

// round 12
// speedup vs baseline: 3.8484x; 1.1522x over previous
#include <cuda_runtime.h>
#include <cuda_fp16.h>
#include <cstdint>

#define N_NODES 10000
#define N_EDGES 640000
#define E_TOT   (N_EDGES + N_NODES)   // 650000
#define H 128
#define NUM_LAYERS 4

#define TE 128
#define NT_TILES ((E_TOT + TE - 1) / TE)   // 5079
#define GRID_EDGE 148
#define THREADS_EDGE 384                   // 8 consumer warps + 4 producer warps

#define LDW 136   // half elems, W tile [n][k]
#define LDZ 136   // half elems, Z tiles [e][k]
#define LDD 132   // f32 elems,  D tile  [e][n]

// SMEM byte offsets
#define O_W   0u
#define O_Z0  34816u
#define ZBUF_BYTES 34816u                  // 128*LDZ*2, two buffers
#define O_D   104448u
#define O_DST 172032u                      // [2][128] ints
#define O_BIAS 173056u
#define SMEM_EDGE_BYTES 173568u

// ---------------- persistent scratch ----------------
__device__ float g_buf0[N_NODES * H];
__device__ float g_buf1[N_NODES * H];
__device__ float g_A[N_NODES * H];
__device__ float g_B[N_NODES * H];
__device__ int   g_es0[E_TOT];
__device__ int   g_ed0[E_TOT];
__device__ int   g_es[E_TOT];   // sorted by dst
__device__ int   g_ed[E_TOT];   // sorted by dst
__device__ int   g_cnt[N_NODES];
__device__ int   g_pos[N_NODES];
__device__ int   g_is64;

// ---------------- mma/ldmatrix helpers ----------------
__device__ __forceinline__ void ldsm_x4(uint32_t& r0, uint32_t& r1, uint32_t& r2,
                                        uint32_t& r3, uint32_t addr) {
    asm volatile("ldmatrix.sync.aligned.m8n8.x4.shared.b16 {%0,%1,%2,%3}, [%4];"
                 : "=r"(r0), "=r"(r1), "=r"(r2), "=r"(r3) : "r"(addr));
}
__device__ __forceinline__ void mma16816(float* d, uint32_t a0, uint32_t a1, uint32_t a2,
                                         uint32_t a3, uint32_t b0, uint32_t b1) {
    asm volatile(
        "mma.sync.aligned.m16n8k16.row.col.f32.f16.f16.f32 "
        "{%0,%1,%2,%3}, {%4,%5,%6,%7}, {%8,%9}, {%0,%1,%2,%3};"
        : "+f"(d[0]), "+f"(d[1]), "+f"(d[2]), "+f"(d[3])
        : "r"(a0), "r"(a1), "r"(a2), "r"(a3), "r"(b0), "r"(b1));
}

// ---------------- edge dtype detect ----------------
__global__ void detect_dtype(const int* __restrict__ ei32) {
    __shared__ int sbad;
    if (threadIdx.x == 0) sbad = 0;
    __syncthreads();
    int bad = 0;
    for (int i = threadIdx.x; i < 1024; i += 256)
        if (ei32[2 * i + 1] != 0) bad = 1;
    if (bad) atomicOr(&sbad, 1);
    __syncthreads();
    if (threadIdx.x == 0) g_is64 = sbad ? 0 : 1;
}

__global__ void zero_cnt() {
    int i = blockIdx.x * blockDim.x + threadIdx.x;
    if (i < N_NODES) g_cnt[i] = 0;
}

// edge prep + histogram of dst
__global__ void prep_edges(const void* __restrict__ ei) {
    int i = blockIdx.x * blockDim.x + threadIdx.x;
    if (i < N_EDGES) {
        int s, d;
        if (g_is64) {
            const long long* p = (const long long*)ei;
            s = (int)p[i];
            d = (int)p[N_EDGES + i];
        } else {
            const int* p = (const int*)ei;
            s = p[i];
            d = p[N_EDGES + i];
        }
        g_es0[i] = s;
        g_ed0[i] = d;
        atomicAdd(&g_cnt[d], 1);
    } else if (i < E_TOT) {
        int n = i - N_EDGES;
        g_es0[i] = n;
        g_ed0[i] = n;
        atomicAdd(&g_cnt[n], 1);
    }
}

// single-block exclusive scan of g_cnt -> g_pos
__global__ void scan_kernel() {
    __shared__ int part[1024];
    int t = threadIdx.x;
    int s = 0;
    int base = t * 10;
    if (t < 1000) {
#pragma unroll
        for (int i = 0; i < 10; i++) s += g_cnt[base + i];
    }
    part[t] = s;
    __syncthreads();
    for (int off = 1; off < 1024; off <<= 1) {
        int v = part[t];
        if (t >= off) v += part[t - off];
        __syncthreads();
        part[t] = v;
        __syncthreads();
    }
    int excl = (t == 0) ? 0 : part[t - 1];
    if (t < 1000) {
        int run = excl;
#pragma unroll
        for (int i = 0; i < 10; i++) {
            int c = g_cnt[base + i];
            g_pos[base + i] = run;
            run += c;
        }
    }
}

__global__ void scatter_kernel() {
    int i = blockIdx.x * blockDim.x + threadIdx.x;
    if (i < E_TOT) {
        int d = g_ed0[i];
        int p = atomicAdd(&g_pos[d], 1);
        g_es[p] = g_es0[i];
        g_ed[p] = d;
    }
}

// ---------------- embed: h0 = x@W_emb + b ----------------
__global__ void embed_kernel(const float* __restrict__ x, const float* __restrict__ W,
                             const float* __restrict__ b, float* __restrict__ h) {
    __shared__ float sx[16][64];
    int n0 = blockIdx.x * 16;
    for (int i = threadIdx.x; i < 16 * 64; i += 128)
        sx[i >> 6][i & 63] = x[n0 * 64 + i];
    __syncthreads();
    int c = threadIdx.x;
    float bc = b[c];
    for (int n = 0; n < 16; n++) {
        float acc = bc;
#pragma unroll 16
        for (int k = 0; k < 64; k++) acc = fmaf(sx[n][k], W[k * 128 + c], acc);
        h[(n0 + n) * 128 + c] = acc;
    }
}

// ---------------- node transform (256 thr): A = h(W1a-W1b)+b1, B = h W1b ----------------
__global__ void node_transform(const float* __restrict__ h, const float* __restrict__ W1l,
                               const float* __restrict__ b1l, float* __restrict__ A,
                               float* __restrict__ B, float* __restrict__ out_init) {
    __shared__ float sh[16][128];
    int n0 = blockIdx.x * 16;
    for (int i = threadIdx.x; i < 16 * 128; i += 256)
        sh[i >> 7][i & 127] = h[n0 * 128 + i];
    __syncthreads();
    int c = threadIdx.x & 127;
    int nh = (threadIdx.x >> 7) * 8;   // node half: 0 or 8
    float a[8], bb[8];
    float bc = b1l[c];
#pragma unroll
    for (int n = 0; n < 8; n++) { a[n] = bc; bb[n] = 0.f; }
    for (int k = 0; k < 128; k++) {
        float wa = W1l[k * 128 + c];
        float wb = W1l[(k + 128) * 128 + c];
        float wd = wa - wb;
#pragma unroll
        for (int n = 0; n < 8; n++) {
            float hv = sh[nh + n][k];
            a[n]  = fmaf(hv, wd, a[n]);
            bb[n] = fmaf(hv, wb, bb[n]);
        }
    }
#pragma unroll
    for (int n = 0; n < 8; n++) {
        int r = (n0 + nh + n) * 128 + c;
        A[r] = a[n];
        B[r] = bb[n];
        out_init[r] = -3.4028234663852886e38f;
    }
}

// ---------------- persistent edge phase: warp-specialized producer/consumer ----------------
__global__ __launch_bounds__(THREADS_EDGE, 1)
void edge_persist(const float* __restrict__ A, const float* __restrict__ B,
                  const float* __restrict__ W2l, const float* __restrict__ b2l,
                  const int* __restrict__ es, const int* __restrict__ ed,
                  float* __restrict__ hout) {
    extern __shared__ __align__(16) char sm[];
    __half* sW   = (__half*)(sm + O_W);
    float* sD    = (float*)(sm + O_D);
    int*   sDst  = (int*)(sm + O_DST);     // [2][128]
    float* sBias = (float*)(sm + O_BIAS);

    int tid = threadIdx.x;
    int lane = tid & 31;
    int w = tid >> 5;

    uint32_t smb = (uint32_t)__cvta_generic_to_shared(sm);

    // one-time: W2^T into fp16: sW[n][k]
    for (int i = tid; i < H * H; i += THREADS_EDGE) {
        int k = i >> 7, n = i & 127;
        sW[n * LDW + k] = __float2half_rn(W2l[i]);
    }
    if (tid < 128) sBias[tid] = b2l[tid];
    __syncthreads();

    bool is_consumer = (w < 8);

    // consumer mapping: er = w>>1 edges [er*32,+32); nc = w&1 cols [nc*64,+64)
    int er = w >> 1;
    int nc = w & 1;
    int g  = lane >> 2;
    int t2 = (lane & 3) * 2;

    // A ldmatrix lane addresses
    uint32_t aoff0 = ((uint32_t)((er * 32 + (lane & 15)) * LDZ + (lane >> 4) * 8)) * 2u;
    uint32_t aoff1 = aoff0 + 16u * LDZ * 2u;
    // B x4 lane addresses: lanes 0-15 -> j slab, lanes 16-31 -> j+1 slab (+8 rows)
    uint32_t brow4 = (uint32_t)(nc * 64 + (lane & 7) + ((lane >> 4) & 1) * 8);
    uint32_t bkh   = (uint32_t)((lane >> 3) & 1) * 8u;
    uint32_t bwoff = smb + O_W + (brow4 * LDW + bkh) * 2u;

    // producer identity: threads 256..383, 1 thread per edge... 128 producers
    int pe = tid - 256;

    auto build = [&](int t, int buf) {
        int ee = t * TE + pe;
        bool vld = ee < E_TOT;
        int d = vld ? __ldg(&ed[ee]) : 0;
        int s = vld ? __ldg(&es[ee]) : 0;
        sDst[buf * 128 + pe] = vld ? d : -1;
        const float4* pa = (const float4*)(A + (size_t)d * 128);
        const float4* pb = (const float4*)(B + (size_t)s * 128);
        __half* sZ = (__half*)(sm + O_Z0 + (uint32_t)buf * ZBUF_BYTES);
#pragma unroll
        for (int i = 0; i < 16; i++) {
            float4 a0 = __ldg(pa + 2 * i), a1 = __ldg(pa + 2 * i + 1);
            float4 b0 = __ldg(pb + 2 * i), b1 = __ldg(pb + 2 * i + 1);
            float v0 = 0.f, v1 = 0.f, v2 = 0.f, v3 = 0.f;
            float v4 = 0.f, v5 = 0.f, v6 = 0.f, v7 = 0.f;
            if (vld) {
                v0 = fmaxf(a0.x + b0.x, 0.f);
                v1 = fmaxf(a0.y + b0.y, 0.f);
                v2 = fmaxf(a0.z + b0.z, 0.f);
                v3 = fmaxf(a0.w + b0.w, 0.f);
                v4 = fmaxf(a1.x + b1.x, 0.f);
                v5 = fmaxf(a1.y + b1.y, 0.f);
                v6 = fmaxf(a1.z + b1.z, 0.f);
                v7 = fmaxf(a1.w + b1.w, 0.f);
            }
            __half2 h0 = __floats2half2_rn(v0, v1);
            __half2 h1 = __floats2half2_rn(v2, v3);
            __half2 h2 = __floats2half2_rn(v4, v5);
            __half2 h3 = __floats2half2_rn(v6, v7);
            uint4 pk;
            pk.x = *(uint32_t*)&h0;
            pk.y = *(uint32_t*)&h1;
            pk.z = *(uint32_t*)&h2;
            pk.w = *(uint32_t*)&h3;
            *(uint4*)(sZ + pe * LDZ + i * 8) = pk;
        }
    };

    auto gemm = [&](int buf) {
        uint32_t zbase = smb + O_Z0 + (uint32_t)buf * ZBUF_BYTES;
        float acc[2][8][4];
#pragma unroll
        for (int f = 0; f < 2; f++)
#pragma unroll
            for (int j = 0; j < 8; j++)
#pragma unroll
                for (int r = 0; r < 4; r++) acc[f][j][r] = 0.f;

#pragma unroll
        for (int k0 = 0; k0 < 8; k0++) {
            uint32_t a0[4], a1[4];
            ldsm_x4(a0[0], a0[1], a0[2], a0[3], zbase + aoff0 + (uint32_t)k0 * 32u);
            ldsm_x4(a1[0], a1[1], a1[2], a1[3], zbase + aoff1 + (uint32_t)k0 * 32u);
#pragma unroll
            for (int j = 0; j < 8; j += 2) {
                uint32_t jb = (uint32_t)(j * 8 * LDW * 2) + (uint32_t)k0 * 32u;
                uint32_t b0, b1, b2, b3;
                ldsm_x4(b0, b1, b2, b3, bwoff + jb);
                mma16816(acc[0][j], a0[0], a0[1], a0[2], a0[3], b0, b1);
                mma16816(acc[1][j], a1[0], a1[1], a1[2], a1[3], b0, b1);
                mma16816(acc[0][j + 1], a0[0], a0[1], a0[2], a0[3], b2, b3);
                mma16816(acc[1][j + 1], a1[0], a1[1], a1[2], a1[3], b2, b3);
            }
        }
#pragma unroll
        for (int f = 0; f < 2; f++) {
            int r0 = er * 32 + f * 16 + g;
#pragma unroll
            for (int j = 0; j < 8; j++) {
                int c = nc * 64 + j * 8 + t2;
                *(float2*)(sD + r0 * LDD + c)       = make_float2(acc[f][j][0], acc[f][j][1]);
                *(float2*)(sD + (r0 + 8) * LDD + c) = make_float2(acc[f][j][2], acc[f][j][3]);
            }
        }
    };

    // epilogue (consumer, 256 thr): 4 quarters of 32 edges, 2 channels/thread
    auto epilogue = [&](int buf) {
        int cp = tid & 63;
        int qq = tid >> 6;          // 0..3 for tid<256
        float2 bias2 = *(float2*)(sBias + cp * 2);
        const int* dstb = sDst + buf * 128;
        int cur = dstb[32 * qq];
        float r0 = -3.4028234663852886e38f, r1 = -3.4028234663852886e38f;
#pragma unroll 4
        for (int ee = 32 * qq; ee < 32 * qq + 32; ee++) {
            int d = dstb[ee];
            float2 v = *(float2*)(sD + ee * LDD + cp * 2);
            v.x += bias2.x;
            v.y += bias2.y;
            if (d != cur) {
                if (cur >= 0) {
                    float* p = hout + (size_t)cur * 128 + cp * 2;
                    if (r0 >= 0.f) atomicMax((int*)p, __float_as_int(r0));
                    else           atomicMin((unsigned int*)p, __float_as_uint(r0));
                    if (r1 >= 0.f) atomicMax((int*)(p + 1), __float_as_int(r1));
                    else           atomicMin((unsigned int*)(p + 1), __float_as_uint(r1));
                }
                cur = d;
                r0 = v.x;
                r1 = v.y;
            } else {
                r0 = fmaxf(r0, v.x);
                r1 = fmaxf(r1, v.y);
            }
        }
        if (cur >= 0) {
            float* p = hout + (size_t)cur * 128 + cp * 2;
            if (r0 >= 0.f) atomicMax((int*)p, __float_as_int(r0));
            else           atomicMin((unsigned int*)p, __float_as_uint(r0));
            if (r1 >= 0.f) atomicMax((int*)(p + 1), __float_as_int(r1));
            else           atomicMin((unsigned int*)(p + 1), __float_as_uint(r1));
        }
    };

    // prologue: producer builds first tile into buf 0
    if (!is_consumer) build(blockIdx.x, 0);
    __syncthreads();

    int it = 0;
    for (int t = blockIdx.x; t < NT_TILES; t += GRID_EDGE, it++) {
        int p = it & 1;
        if (is_consumer) {
            gemm(p);
            asm volatile("bar.sync 1, 256;" ::: "memory");   // sD ready among consumers
            epilogue(p);
        } else {
            int tn = t + GRID_EDGE;
            if (tn < NT_TILES) build(tn, 1 - p);
        }
        __syncthreads();
    }
}

// ---------------- final: out = h@W_fc + b ----------------
__global__ void final_kernel(const float* __restrict__ h, const float* __restrict__ W,
                             const float* __restrict__ b, float* __restrict__ out) {
    __shared__ float sh[16][128];
    int n0 = blockIdx.x * 16;
    for (int i = threadIdx.x; i < 16 * 128; i += 128)
        sh[i >> 7][i & 127] = h[n0 * 128 + i];
    __syncthreads();
    int c = threadIdx.x;
    float bc = b[c];
    for (int n = 0; n < 16; n++) {
        float acc = bc;
#pragma unroll 8
        for (int k = 0; k < 128; k++) acc = fmaf(sh[n][k], W[k * 128 + c], acc);
        out[(n0 + n) * 128 + c] = acc;
    }
}

extern "C" void kernel_launch(void* const* d_in, const int* in_sizes, int n_in,
                              void* d_out, int out_size) {
    const float* x    = (const float*)d_in[0];
    const void*  ei   = d_in[1];
    const float* Wemb = (const float*)d_in[2];
    const float* bemb = (const float*)d_in[3];
    const float* W1   = (const float*)d_in[4];
    const float* b1   = (const float*)d_in[5];
    const float* W2   = (const float*)d_in[6];
    const float* b2   = (const float*)d_in[7];
    const float* Wfc  = (const float*)d_in[8];
    const float* bfc  = (const float*)d_in[9];
    float* out = (float*)d_out;

    float *buf0, *buf1, *Ap, *Bp;
    int *es, *ed;
    cudaGetSymbolAddress((void**)&buf0, g_buf0);
    cudaGetSymbolAddress((void**)&buf1, g_buf1);
    cudaGetSymbolAddress((void**)&Ap,   g_A);
    cudaGetSymbolAddress((void**)&Bp,   g_B);
    cudaGetSymbolAddress((void**)&es,   g_es);
    cudaGetSymbolAddress((void**)&ed,   g_ed);

    cudaFuncSetAttribute(edge_persist, cudaFuncAttributeMaxDynamicSharedMemorySize,
                         SMEM_EDGE_BYTES);

    detect_dtype<<<1, 256>>>((const int*)ei);
    zero_cnt<<<(N_NODES + 255) / 256, 256>>>();
    prep_edges<<<(E_TOT + 255) / 256, 256>>>(ei);
    scan_kernel<<<1, 1024>>>();
    scatter_kernel<<<(E_TOT + 255) / 256, 256>>>();
    embed_kernel<<<N_NODES / 16, 128>>>(x, Wemb, bemb, buf0);

    float* hin = buf0;
    float* hout = buf1;
    for (int l = 0; l < NUM_LAYERS; l++) {
        node_transform<<<N_NODES / 16, 256>>>(hin, W1 + l * 2 * H * H, b1 + l * H,
                                              Ap, Bp, hout);
        edge_persist<<<GRID_EDGE, THREADS_EDGE, SMEM_EDGE_BYTES>>>(Ap, Bp, W2 + l * H * H,
                                                                   b2 + l * H, es, ed, hout);
        float* t = hin; hin = hout; hout = t;
    }
    final_kernel<<<N_NODES / 16, 128>>>(hin, Wfc, bfc, out);
}